// round 12
// baseline (speedup 1.0000x reference)
#include <cuda_runtime.h>
#include <cuda_bf16.h>
#include <cuda_fp16.h>
#include <stdint.h>

#define NNODES 50000
#define NPAD   50048            // 391 * 128
#define NEDGES 800000
#define IN_DIM 256
#define HEADS  8
#define NH     512

// ---------------- device scratch ----------------
__device__ __align__(128) __nv_bfloat16 g_Ah[(size_t)NPAD*IN_DIM];
__device__ __align__(128) __nv_bfloat16 g_Al[(size_t)NPAD*IN_DIM];
__device__ __align__(128) __nv_bfloat16 g_Bth[NH*IN_DIM];
__device__ __align__(128) __nv_bfloat16 g_Btl[NH*IN_DIM];
__device__ __align__(128) __half g_Wh16[(size_t)NNODES*NH];   // 51.2 MB (fp16 Wh)
__device__ __align__(16)  float g_s[NNODES*16];
__device__ unsigned g_mkey[16];
__device__ float g_Z[HEADS];
__device__ float g_gate[HEADS];
__device__ int g_cnt[NNODES];
__device__ int g_colptr[NNODES+1];
__device__ int g_cur[NNODES];
__device__ int g_bsum[256];
__device__ int g_srow[NEDGES];
__device__ int g_bar;                  // global barrier for k_zscatter (reset in k_setup)
__device__ int g_bar2;                 // global barrier for k_scan

// ---------------- helpers ----------------
__device__ __forceinline__ unsigned fkey(float f){
    unsigned b = __float_as_uint(f);
    return (b & 0x80000000u) ? ~b : (b | 0x80000000u);
}
__device__ __forceinline__ float fdec(unsigned k){
    return (k & 0x80000000u) ? __uint_as_float(k ^ 0x80000000u) : __uint_as_float(~k);
}
__device__ __forceinline__ uint32_t s2u(const void* p){
    return (uint32_t)__cvta_generic_to_shared(p);
}
__device__ __forceinline__ void cpa16(uint32_t dst, const void* src){
    asm volatile("cp.async.cg.shared.global [%0], [%1], 16;" :: "r"(dst), "l"(src));
}
__device__ __forceinline__ void ldsm4(uint32_t* r, uint32_t addr){
    asm volatile("ldmatrix.sync.aligned.m8n8.x4.shared.b16 {%0,%1,%2,%3}, [%4];"
        : "=r"(r[0]), "=r"(r[1]), "=r"(r[2]), "=r"(r[3]) : "r"(addr));
}
__device__ __forceinline__ void mma_bf16(float* d, const uint32_t* a, uint32_t b0, uint32_t b1){
    asm volatile("mma.sync.aligned.m16n8k16.row.col.f32.bf16.bf16.f32 "
        "{%0,%1,%2,%3},{%4,%5,%6,%7},{%8,%9},{%0,%1,%2,%3};"
        : "+f"(d[0]), "+f"(d[1]), "+f"(d[2]), "+f"(d[3])
        : "r"(a[0]), "r"(a[1]), "r"(a[2]), "r"(a[3]), "r"(b0), "r"(b1));
}

// ---------------- fused setup ----------------
__global__ void k_setup(const float* __restrict__ x, const int* __restrict__ ei,
                        const float* __restrict__ W, const float* __restrict__ gate,
                        float* __restrict__ out){
    int tid = blockIdx.x*blockDim.x + threadIdx.x;
    if (tid < 8)  g_Z[tid] = 0.f;
    if (tid < 16) g_mkey[tid] = 0u;
    if (tid == 0){
        g_bar  = 0;
        g_bar2 = 0;
        float m = -1e30f;
        for (int h = 0; h < HEADS; h++) m = fmaxf(m, gate[h]);
        float ex[HEADS]; float z = 0.f;
        for (int h = 0; h < HEADS; h++){ ex[h] = __expf(gate[h]-m); z += ex[h]; }
        for (int h = 0; h < HEADS; h++) g_gate[h] = ex[h]/z;
    }
    if (tid < NNODES*16)
        reinterpret_cast<float4*>(out)[tid] = make_float4(0.f,0.f,0.f,0.f);
    if (tid < NEDGES) atomicAdd(&g_cnt[ei[NEDGES + tid]], 1);
    if (tid < NH*IN_DIM){
        int n = tid >> 8, d = tid & 255;
        int h = n >> 6, o = n & 63;
        float v = W[(size_t)h*IN_DIM*64 + d*64 + o];
        __nv_bfloat16 hb = __float2bfloat16(v);
        __nv_bfloat16 lb = __float2bfloat16(v - __bfloat162float(hb));
        g_Bth[tid] = hb;
        g_Btl[tid] = lb;
    }
    if (tid < NPAD*IN_DIM/4){
        int base = tid*4;
        int row = base / IN_DIM;
        float4 v = make_float4(0.f,0.f,0.f,0.f);
        if (row < NNODES) v = *reinterpret_cast<const float4*>(x + base);
        float vv[4] = {v.x, v.y, v.z, v.w};
        unsigned short hb[4], lb[4];
#pragma unroll
        for (int j = 0; j < 4; j++){
            __nv_bfloat16 h = __float2bfloat16(vv[j]);
            __nv_bfloat16 l = __float2bfloat16(vv[j] - __bfloat162float(h));
            hb[j] = __bfloat16_as_ushort(h);
            lb[j] = __bfloat16_as_ushort(l);
        }
        uint2 ph = make_uint2((unsigned)hb[0] | ((unsigned)hb[1]<<16),
                              (unsigned)hb[2] | ((unsigned)hb[3]<<16));
        uint2 pl = make_uint2((unsigned)lb[0] | ((unsigned)lb[1]<<16),
                              (unsigned)lb[2] | ((unsigned)lb[3]<<16));
        *reinterpret_cast<uint2*>(reinterpret_cast<char*>(g_Ah) + (size_t)base*2) = ph;
        *reinterpret_cast<uint2*>(reinterpret_cast<char*>(g_Al) + (size_t)base*2) = pl;
    }
}

// ---------------- merged CSC scan (persistent 196 CTAs, software barrier) ----------------
__global__ __launch_bounds__(256,2) void k_scan(){
    __shared__ int sd[256];
    __shared__ int s_off;
    int tid = threadIdx.x;
    const int nb = (NNODES + 255)/256;     // 196
    // phase 1: block-local scan
    int i = blockIdx.x*256 + tid;
    int v = (i < NNODES) ? g_cnt[i] : 0;
    if (i < NNODES) g_cnt[i] = 0;
    sd[tid] = v; __syncthreads();
    for (int off = 1; off < 256; off <<= 1){
        int t = (tid >= off) ? sd[tid - off] : 0;
        __syncthreads();
        sd[tid] += t;
        __syncthreads();
    }
    int local = sd[tid] - v;
    if (tid == 255) g_bsum[blockIdx.x] = sd[255];
    // global barrier
    if (tid == 0){
        __threadfence();
        atomicAdd(&g_bar2, 1);
        while (*(volatile int*)&g_bar2 < nb) {}
        __threadfence();
    }
    __syncthreads();
    // phase 2: every block redundantly scans block sums, applies its offset
    int bv = (tid < nb) ? g_bsum[tid] : 0;
    sd[tid] = bv; __syncthreads();
    for (int off = 1; off < 256; off <<= 1){
        int t = (tid >= off) ? sd[tid - off] : 0;
        __syncthreads();
        sd[tid] += t;
        __syncthreads();
    }
    if (tid == (int)blockIdx.x) s_off = sd[tid] - bv;
    __syncthreads();
    if (i < NNODES){
        int p = local + s_off;
        g_colptr[i] = p;
        g_cur[i]    = p;
    }
    if (blockIdx.x == 0 && tid == 0) g_colptr[NNODES] = NEDGES;
}

// ---------------- big kernel: fused 3-product stage loop (unchanged, at HMMA ceiling) ----------------
#define TILE     8192
#define ST       32768
#define OFF_A    0
#define OFF_BIAS 98304
#define OFF_SA   100352
#define OFF_SSM  104448
#define OFF_SMK  112640
#define SMEM_BIG 112704

__device__ __forceinline__ void load_tile32(uint32_t dstbase, const __nv_bfloat16* __restrict__ src,
                                            int tid){
#pragma unroll
    for (int i = 0; i < 2; i++){
        int idx = tid + i*256;
        int r = idx >> 2, qq = idx & 3;
        uint32_t off = (uint32_t)(r*64 + ((qq ^ ((r >> 1) & 3)) << 4));
        cpa16(dstbase + off, src + (size_t)r*IN_DIM + qq*8);
    }
}

__device__ __forceinline__ void gemm_stage(uint32_t sb_st, int wm, int wn, int lane,
                                           float d[4][4][4]){
    int lr = lane & 15;
    int qh = lane >> 4;
    uint32_t arow[4], brow[2];
    int asw[4], bsw[2];
#pragma unroll
    for (int mi = 0; mi < 4; mi++){
        int row = wm + mi*16 + lr;
        arow[mi] = sb_st + row*64;
        asw[mi]  = (row >> 1) & 3;
    }
#pragma unroll
    for (int bi = 0; bi < 2; bi++){
        int row = wn + bi*16 + lr;
        brow[bi] = sb_st + 2*TILE + row*64;
        bsw[bi]  = (row >> 1) & 3;
    }
#pragma unroll
    for (int ks = 0; ks < 2; ks++){
        int q = ks*2 + qh;
        uint32_t af[4][4], bfh[2][4], bfl[2][4];
#pragma unroll
        for (int mi = 0; mi < 4; mi++)
            ldsm4(af[mi], arow[mi] + ((q ^ asw[mi]) << 4));
#pragma unroll
        for (int bi = 0; bi < 2; bi++){
            uint32_t boff = ((q ^ bsw[bi]) << 4);
            ldsm4(bfh[bi], brow[bi] + boff);
            ldsm4(bfl[bi], brow[bi] + TILE + boff);
        }
#pragma unroll
        for (int mi = 0; mi < 4; mi++)
#pragma unroll
            for (int ni = 0; ni < 4; ni++){
                int bi = ni >> 1, sub = ni & 1;
                mma_bf16(d[mi][ni], af[mi], bfh[bi][sub], bfh[bi][sub + 2]);
                mma_bf16(d[mi][ni], af[mi], bfl[bi][sub], bfl[bi][sub + 2]);
            }
#pragma unroll
        for (int mi = 0; mi < 4; mi++)
            ldsm4(af[mi], arow[mi] + TILE + ((q ^ asw[mi]) << 4));
#pragma unroll
        for (int mi = 0; mi < 4; mi++)
#pragma unroll
            for (int ni = 0; ni < 4; ni++){
                int bi = ni >> 1, sub = ni & 1;
                mma_bf16(d[mi][ni], af[mi], bfh[bi][sub], bfh[bi][sub + 2]);
            }
    }
}

// grid = (4, 391)
__global__ __launch_bounds__(256,2) void k_big(const float* __restrict__ bias,
                                               const float* __restrict__ a_vec,
                                               const int* __restrict__ ei){
    extern __shared__ char smem[];
    uint32_t sb = s2u(smem);
    float*    s_bias = (float*)(smem + OFF_BIAS);
    float*    s_a    = (float*)(smem + OFF_SA);
    float*    s_sm   = (float*)(smem + OFF_SSM);
    unsigned* s_mk   = (unsigned*)(smem + OFF_SMK);

    int tid = threadIdx.x, wid = tid >> 5, lane = tid & 31;
    int wm = (wid >> 2)*64, wn = (wid & 3)*32;
    int m0 = blockIdx.y*128, n0 = blockIdx.x*128;

    for (int i = tid; i < 512;  i += 256) s_bias[i] = bias[i];
    for (int i = tid; i < 1024; i += 256) s_a[i]    = a_vec[i];
    for (int i = tid; i < 2048; i += 256) s_sm[i]   = 0.f;
    if (tid < 16) s_mk[tid] = 0u;

    float d[4][4][4];
#pragma unroll
    for (int mi = 0; mi < 4; mi++)
#pragma unroll
        for (int ni = 0; ni < 4; ni++)
#pragma unroll
            for (int k = 0; k < 4; k++) d[mi][ni][k] = 0.f;

    const __nv_bfloat16* Abase  = g_Ah  + (size_t)m0*IN_DIM;
    const __nv_bfloat16* Albase = g_Al  + (size_t)m0*IN_DIM;
    const __nv_bfloat16* Bbase  = g_Bth + (size_t)n0*IN_DIM;
    const __nv_bfloat16* Blbase = g_Btl + (size_t)n0*IN_DIM;

#pragma unroll
    for (int c = 0; c < 2; c++){
        uint32_t st = sb + OFF_A + c*ST;
        load_tile32(st,          Abase  + c*32, tid);
        load_tile32(st +   TILE, Albase + c*32, tid);
        load_tile32(st + 2*TILE, Bbase  + c*32, tid);
        load_tile32(st + 3*TILE, Blbase + c*32, tid);
        asm volatile("cp.async.commit_group;" ::: "memory");
    }

    // CSC reorder: 512 edges per CTA, hidden behind prologue loads
    {
        int cta = blockIdx.y*4 + blockIdx.x;
#pragma unroll
        for (int r = 0; r < 2; r++){
            int e = cta*512 + r*256 + tid;
            if (e < NEDGES){
                int row = ei[e], col = ei[NEDGES + e];
                int pos = atomicAdd(&g_cur[col], 1);
                g_srow[pos] = row;
            }
        }
    }

    for (int c = 0; c < 8; c++){
        asm volatile("cp.async.wait_group 1;" ::: "memory");
        __syncthreads();
        int cn = c + 2;
        if (cn < 8){
            uint32_t st = sb + OFF_A + (cn % 3)*ST;
            load_tile32(st,          Abase  + cn*32, tid);
            load_tile32(st +   TILE, Albase + cn*32, tid);
            load_tile32(st + 2*TILE, Bbase  + cn*32, tid);
            load_tile32(st + 3*TILE, Blbase + cn*32, tid);
        }
        asm volatile("cp.async.commit_group;" ::: "memory");
        gemm_stage(sb + OFF_A + (c % 3)*ST, wm, wn, lane, d);
    }

    // -------- epilogue --------
    int h = (n0 + wn) >> 6;
    const float* aS = s_a + h*128;
    const float* aD = s_a + h*128 + 64;
    float accS[4][2], accD[4][2];
#pragma unroll
    for (int mi = 0; mi < 4; mi++){ accS[mi][0]=accS[mi][1]=accD[mi][0]=accD[mi][1]=0.f; }

#pragma unroll
    for (int mi = 0; mi < 4; mi++){
#pragma unroll
        for (int ni = 0; ni < 4; ni++){
            int C = wn + ni*8 + (lane & 3)*2;
            int o = C & 63;
            float b0 = s_bias[n0 + C], b1 = s_bias[n0 + C + 1];
#pragma unroll
            for (int rr = 0; rr < 2; rr++){
                float v0 = d[mi][ni][rr*2 + 0] + b0;
                float v1 = d[mi][ni][rr*2 + 1] + b1;
                int R = wm + mi*16 + (lane >> 2) + rr*8;
                int gm = m0 + R;
                if (gm < NNODES){
                    __half2 hv = __floats2half2_rn(v0, v1);
                    *reinterpret_cast<__half2*>(g_Wh16 + (size_t)gm*NH + n0 + C) = hv;
                }
                accS[mi][rr] += v0*aS[o] + v1*aS[o+1];
                accD[mi][rr] += v0*aD[o] + v1*aD[o+1];
            }
        }
    }
#pragma unroll
    for (int mi = 0; mi < 4; mi++)
#pragma unroll
        for (int rr = 0; rr < 2; rr++){
            float vs = accS[mi][rr], vd = accD[mi][rr];
            vs += __shfl_xor_sync(0xffffffffu, vs, 1);
            vs += __shfl_xor_sync(0xffffffffu, vs, 2);
            vd += __shfl_xor_sync(0xffffffffu, vd, 1);
            vd += __shfl_xor_sync(0xffffffffu, vd, 2);
            if ((lane & 3) == 0){
                int R = wm + mi*16 + (lane >> 2) + rr*8;
                atomicAdd(&s_sm[R*16 + h],     vs);
                atomicAdd(&s_sm[R*16 + 8 + h], vd);
            }
        }
    __syncthreads();
    int h0 = n0 >> 6;
    for (int i = tid; i < 512; i += 256){
        int r = i >> 2, jj = i & 3;
        int j = h0 + (jj & 1) + (jj >> 1)*8;
        int gm = m0 + r;
        if (gm < NNODES){
            float v = s_sm[r*16 + j];
            g_s[gm*16 + j] = v;
            atomicMax(&s_mk[j], fkey(v));
        }
    }
    __syncthreads();
    if (tid < 4){
        int j = h0 + (tid & 1) + (tid >> 1)*8;
        unsigned k = s_mk[j];
        if (k) atomicMax(&g_mkey[j], k);
    }
}

// ---------------- fused Z + scatter: persistent 296 CTAs, 2 phases, global barrier ----------------
#define NWARPS_TOT 2368                 // 296 CTAs * 8 warps

__global__ __launch_bounds__(256,2) void k_zscatter(float* __restrict__ out){
    __shared__ float sMs[8];
    __shared__ float sc[8];
    int tid = threadIdx.x, warp = tid >> 5, lane = tid & 31;
    if (tid < 8){
        float m = fdec(g_mkey[tid]) + fdec(g_mkey[8 + tid]);
        sMs[tid] = (m > 0.f) ? m : 0.01f*m;
    }
    __syncthreads();
    int hh  = lane & 7;
    int sub = lane >> 3;                 // edge slot 0..3
    float Mh = sMs[hh];
    int gw = blockIdx.x*8 + warp;        // 0..2367

    // -------- phase 1: per-head Z over CSC order --------
    float zacc = 0.f;
    for (int c = gw; c < NNODES; c += NWARPS_TOT){
        int p0 = g_colptr[c], p1 = g_colptr[c+1];
        if (p0 == p1) continue;
        float sd = g_s[c*16 + 8 + hh];
        for (int p = p0; p < p1; p += 4){
            int idx = p + sub;
            int rowv = g_srow[min(idx, p1-1)];
            float t = g_s[rowv*16 + hh] + sd;
            t = (t > 0.f) ? t : 0.01f*t;
            float w = __expf(t - Mh);
            zacc += (idx < p1) ? w : 0.f;
        }
    }
    zacc += __shfl_xor_sync(0xffffffffu, zacc, 16);
    zacc += __shfl_xor_sync(0xffffffffu, zacc, 8);
    if (lane < 8) atomicAdd(&g_Z[lane], zacc);
    __syncthreads();
    // -------- global barrier --------
    if (tid == 0){
        __threadfence();
        atomicAdd(&g_bar, 1);
        while (*(volatile int*)&g_bar < 296) {}
        __threadfence();
    }
    __syncthreads();
    if (tid < 8) sc[tid] = g_gate[tid] / g_Z[tid];
    __syncthreads();
    float ch = sc[hh];

    // -------- phase 2: scatter (4-edge unroll) --------
    for (int c = gw; c < NNODES; c += NWARPS_TOT){
        int p0 = g_colptr[c], p1 = g_colptr[c+1];
        if (p0 == p1) continue;
        const __half* wp = g_Wh16 + (size_t)c*NH;
        float whv[16];
#pragma unroll
        for (int h = 0; h < 8; h++){
            whv[h]     = __half2float(wp[h*64 + lane]);
            whv[8 + h] = __half2float(wp[h*64 + 32 + lane]);
        }
        float sd = g_s[c*16 + 8 + hh];
        for (int p = p0; p < p1; p += 4){
            int idx = p + sub;
            int rowv = g_srow[min(idx, p1-1)];
            float t = g_s[rowv*16 + hh] + sd;
            t = (t > 0.f) ? t : 0.01f*t;
            float wv = ch * __expf(t - Mh);
            float a0l = 0.f, a0h = 0.f, a1l = 0.f, a1h = 0.f;
            float a2l = 0.f, a2h = 0.f, a3l = 0.f, a3h = 0.f;
#pragma unroll
            for (int h = 0; h < 8; h++){
                float w0 = __shfl_sync(0xffffffffu, wv, h);
                float w1 = __shfl_sync(0xffffffffu, wv, 8 + h);
                float w2 = __shfl_sync(0xffffffffu, wv, 16 + h);
                float w3 = __shfl_sync(0xffffffffu, wv, 24 + h);
                a0l += w0*whv[h];  a0h += w0*whv[8+h];
                a1l += w1*whv[h];  a1h += w1*whv[8+h];
                a2l += w2*whv[h];  a2h += w2*whv[8+h];
                a3l += w3*whv[h];  a3h += w3*whv[8+h];
            }
            int r0 = __shfl_sync(0xffffffffu, rowv, 0);
            int r1 = __shfl_sync(0xffffffffu, rowv, 8);
            int r2 = __shfl_sync(0xffffffffu, rowv, 16);
            int r3 = __shfl_sync(0xffffffffu, rowv, 24);
            atomicAdd(out + (size_t)r0*64 + lane,      a0l);
            atomicAdd(out + (size_t)r0*64 + 32 + lane, a0h);
            if (p + 1 < p1){
                atomicAdd(out + (size_t)r1*64 + lane,      a1l);
                atomicAdd(out + (size_t)r1*64 + 32 + lane, a1h);
            }
            if (p + 2 < p1){
                atomicAdd(out + (size_t)r2*64 + lane,      a2l);
                atomicAdd(out + (size_t)r2*64 + 32 + lane, a2h);
            }
            if (p + 3 < p1){
                atomicAdd(out + (size_t)r3*64 + lane,      a3l);
                atomicAdd(out + (size_t)r3*64 + 32 + lane, a3h);
            }
        }
    }
}

// ---------------- launch ----------------
extern "C" void kernel_launch(void* const* d_in, const int* in_sizes, int n_in,
                              void* d_out, int out_size){
    const float* x    = (const float*)d_in[0];
    const int*   ei   = (const int*)  d_in[1];
    const float* W    = (const float*)d_in[2];
    const float* b    = (const float*)d_in[3];
    const float* a    = (const float*)d_in[4];
    const float* gate = (const float*)d_in[5];
    float* out = (float*)d_out;

    cudaFuncSetAttribute(k_big, cudaFuncAttributeMaxDynamicSharedMemorySize, SMEM_BIG);

    k_setup<<<(NPAD*IN_DIM/4 + 255)/256, 256>>>(x, ei, W, gate, out);
    k_scan<<<(NNODES + 255)/256, 256>>>();          // 196 persistent CTAs, internal barrier
    dim3 gg(4, NPAD/128);
    k_big<<<gg, 256, SMEM_BIG>>>(b, a, ei);
    k_zscatter<<<296, 256>>>(out);                  // persistent, internal barrier; ncu slot
}

// round 13
// speedup vs baseline: 1.2077x; 1.2077x over previous
#include <cuda_runtime.h>
#include <cuda_bf16.h>
#include <cuda_fp16.h>
#include <stdint.h>

#define NNODES 50000
#define NPAD   50048            // 391 * 128
#define NEDGES 800000
#define IN_DIM 256
#define HEADS  8
#define NH     512

// ---------------- device scratch ----------------
__device__ __align__(128) __nv_bfloat16 g_Ah[(size_t)NPAD*IN_DIM];
__device__ __align__(128) __nv_bfloat16 g_Al[(size_t)NPAD*IN_DIM];
__device__ __align__(128) __nv_bfloat16 g_Bth[NH*IN_DIM];
__device__ __align__(128) __nv_bfloat16 g_Btl[NH*IN_DIM];
__device__ __align__(128) __half g_Wh16[(size_t)NNODES*NH];   // 51.2 MB (fp16 Wh)
__device__ __align__(16)  float g_s[NNODES*16];
__device__ unsigned g_mkey[16];
__device__ float g_Z[HEADS];
__device__ float g_gate[HEADS];
__device__ int g_cnt[NNODES];          // zeroed by scan1 for next run
__device__ int g_colptr[NNODES+1];
__device__ int g_cur[NNODES];
__device__ int g_bsum[256];
__device__ int g_srow[NEDGES];

// ---------------- helpers ----------------
__device__ __forceinline__ unsigned fkey(float f){
    unsigned b = __float_as_uint(f);
    return (b & 0x80000000u) ? ~b : (b | 0x80000000u);
}
__device__ __forceinline__ float fdec(unsigned k){
    return (k & 0x80000000u) ? __uint_as_float(k ^ 0x80000000u) : __uint_as_float(~k);
}
__device__ __forceinline__ uint32_t s2u(const void* p){
    return (uint32_t)__cvta_generic_to_shared(p);
}
__device__ __forceinline__ void cpa16(uint32_t dst, const void* src){
    asm volatile("cp.async.cg.shared.global [%0], [%1], 16;" :: "r"(dst), "l"(src));
}
__device__ __forceinline__ void ldsm4(uint32_t* r, uint32_t addr){
    asm volatile("ldmatrix.sync.aligned.m8n8.x4.shared.b16 {%0,%1,%2,%3}, [%4];"
        : "=r"(r[0]), "=r"(r[1]), "=r"(r[2]), "=r"(r[3]) : "r"(addr));
}
__device__ __forceinline__ void mma_bf16(float* d, const uint32_t* a, uint32_t b0, uint32_t b1){
    asm volatile("mma.sync.aligned.m16n8k16.row.col.f32.bf16.bf16.f32 "
        "{%0,%1,%2,%3},{%4,%5,%6,%7},{%8,%9},{%0,%1,%2,%3};"
        : "+f"(d[0]), "+f"(d[1]), "+f"(d[2]), "+f"(d[3])
        : "r"(a[0]), "r"(a[1]), "r"(a[2]), "r"(a[3]), "r"(b0), "r"(b1));
}

// ---------------- fused setup ----------------
__global__ void k_setup(const float* __restrict__ x, const int* __restrict__ ei,
                        const float* __restrict__ W, const float* __restrict__ gate,
                        float* __restrict__ out){
    int tid = blockIdx.x*blockDim.x + threadIdx.x;
    if (tid < 8)  g_Z[tid] = 0.f;
    if (tid < 16) g_mkey[tid] = 0u;
    if (tid == 0){
        float m = -1e30f;
        for (int h = 0; h < HEADS; h++) m = fmaxf(m, gate[h]);
        float ex[HEADS]; float z = 0.f;
        for (int h = 0; h < HEADS; h++){ ex[h] = __expf(gate[h]-m); z += ex[h]; }
        for (int h = 0; h < HEADS; h++) g_gate[h] = ex[h]/z;
    }
    if (tid < NNODES*16)
        reinterpret_cast<float4*>(out)[tid] = make_float4(0.f,0.f,0.f,0.f);
    if (tid < NEDGES) atomicAdd(&g_cnt[ei[NEDGES + tid]], 1);
    if (tid < NH*IN_DIM){
        int n = tid >> 8, d = tid & 255;
        int h = n >> 6, o = n & 63;
        float v = W[(size_t)h*IN_DIM*64 + d*64 + o];
        __nv_bfloat16 hb = __float2bfloat16(v);
        __nv_bfloat16 lb = __float2bfloat16(v - __bfloat162float(hb));
        g_Bth[tid] = hb;
        g_Btl[tid] = lb;
    }
    if (tid < NPAD*IN_DIM/4){
        int base = tid*4;
        int row = base / IN_DIM;
        float4 v = make_float4(0.f,0.f,0.f,0.f);
        if (row < NNODES) v = *reinterpret_cast<const float4*>(x + base);
        float vv[4] = {v.x, v.y, v.z, v.w};
        unsigned short hb[4], lb[4];
#pragma unroll
        for (int j = 0; j < 4; j++){
            __nv_bfloat16 h = __float2bfloat16(vv[j]);
            __nv_bfloat16 l = __float2bfloat16(vv[j] - __bfloat162float(h));
            hb[j] = __bfloat16_as_ushort(h);
            lb[j] = __bfloat16_as_ushort(l);
        }
        uint2 ph = make_uint2((unsigned)hb[0] | ((unsigned)hb[1]<<16),
                              (unsigned)hb[2] | ((unsigned)hb[3]<<16));
        uint2 pl = make_uint2((unsigned)lb[0] | ((unsigned)lb[1]<<16),
                              (unsigned)lb[2] | ((unsigned)lb[3]<<16));
        *reinterpret_cast<uint2*>(reinterpret_cast<char*>(g_Ah) + (size_t)base*2) = ph;
        *reinterpret_cast<uint2*>(reinterpret_cast<char*>(g_Al) + (size_t)base*2) = pl;
    }
}

// ---------------- CSC scans (scan1 + merged scan23) ----------------
__global__ void k_scan1(){
    __shared__ int sd[256];
    int tid = threadIdx.x;
    int i = blockIdx.x*256 + tid;
    int v = (i < NNODES) ? g_cnt[i] : 0;
    if (i < NNODES) g_cnt[i] = 0;
    sd[tid] = v; __syncthreads();
    for (int off = 1; off < 256; off <<= 1){
        int t = (tid >= off) ? sd[tid - off] : 0;
        __syncthreads();
        sd[tid] += t;
        __syncthreads();
    }
    if (i < NNODES) g_colptr[i] = sd[tid] - v;
    if (tid == 255) g_bsum[blockIdx.x] = sd[255];
}
__global__ void k_scan23(){
    __shared__ int sd[256];
    __shared__ int s_off;
    int tid = threadIdx.x;
    const int nb = (NNODES + 255)/256;
    int v = (tid < nb) ? g_bsum[tid] : 0;
    sd[tid] = v; __syncthreads();
    for (int off = 1; off < 256; off <<= 1){
        int t = (tid >= off) ? sd[tid - off] : 0;
        __syncthreads();
        sd[tid] += t;
        __syncthreads();
    }
    if (tid == (int)blockIdx.x) s_off = sd[tid] - v;
    __syncthreads();
    int i = blockIdx.x*256 + tid;
    if (i < NNODES){
        int p = g_colptr[i] + s_off;
        g_colptr[i] = p;
        g_cur[i]    = p;
    }
    if (blockIdx.x == 0 && tid == 0) g_colptr[NNODES] = NEDGES;
}

// ---------------- big kernel: fused 3-product stage loop (HMMA ceiling) ----------------
#define TILE     8192
#define ST       32768
#define OFF_A    0
#define OFF_BIAS 98304
#define OFF_SA   100352
#define OFF_SSM  104448
#define OFF_SMK  112640
#define SMEM_BIG 112704

__device__ __forceinline__ void load_tile32(uint32_t dstbase, const __nv_bfloat16* __restrict__ src,
                                            int tid){
#pragma unroll
    for (int i = 0; i < 2; i++){
        int idx = tid + i*256;
        int r = idx >> 2, qq = idx & 3;
        uint32_t off = (uint32_t)(r*64 + ((qq ^ ((r >> 1) & 3)) << 4));
        cpa16(dstbase + off, src + (size_t)r*IN_DIM + qq*8);
    }
}

__device__ __forceinline__ void gemm_stage(uint32_t sb_st, int wm, int wn, int lane,
                                           float d[4][4][4]){
    int lr = lane & 15;
    int qh = lane >> 4;
    uint32_t arow[4], brow[2];
    int asw[4], bsw[2];
#pragma unroll
    for (int mi = 0; mi < 4; mi++){
        int row = wm + mi*16 + lr;
        arow[mi] = sb_st + row*64;
        asw[mi]  = (row >> 1) & 3;
    }
#pragma unroll
    for (int bi = 0; bi < 2; bi++){
        int row = wn + bi*16 + lr;
        brow[bi] = sb_st + 2*TILE + row*64;
        bsw[bi]  = (row >> 1) & 3;
    }
#pragma unroll
    for (int ks = 0; ks < 2; ks++){
        int q = ks*2 + qh;
        uint32_t af[4][4], bfh[2][4], bfl[2][4];
#pragma unroll
        for (int mi = 0; mi < 4; mi++)
            ldsm4(af[mi], arow[mi] + ((q ^ asw[mi]) << 4));
#pragma unroll
        for (int bi = 0; bi < 2; bi++){
            uint32_t boff = ((q ^ bsw[bi]) << 4);
            ldsm4(bfh[bi], brow[bi] + boff);
            ldsm4(bfl[bi], brow[bi] + TILE + boff);
        }
#pragma unroll
        for (int mi = 0; mi < 4; mi++)
#pragma unroll
            for (int ni = 0; ni < 4; ni++){
                int bi = ni >> 1, sub = ni & 1;
                mma_bf16(d[mi][ni], af[mi], bfh[bi][sub], bfh[bi][sub + 2]);
                mma_bf16(d[mi][ni], af[mi], bfl[bi][sub], bfl[bi][sub + 2]);
            }
#pragma unroll
        for (int mi = 0; mi < 4; mi++)
            ldsm4(af[mi], arow[mi] + TILE + ((q ^ asw[mi]) << 4));
#pragma unroll
        for (int mi = 0; mi < 4; mi++)
#pragma unroll
            for (int ni = 0; ni < 4; ni++){
                int bi = ni >> 1, sub = ni & 1;
                mma_bf16(d[mi][ni], af[mi], bfh[bi][sub], bfh[bi][sub + 2]);
            }
    }
}

// grid = (4, 391)
__global__ __launch_bounds__(256,2) void k_big(const float* __restrict__ bias,
                                               const float* __restrict__ a_vec,
                                               const int* __restrict__ ei){
    extern __shared__ char smem[];
    uint32_t sb = s2u(smem);
    float*    s_bias = (float*)(smem + OFF_BIAS);
    float*    s_a    = (float*)(smem + OFF_SA);
    float*    s_sm   = (float*)(smem + OFF_SSM);
    unsigned* s_mk   = (unsigned*)(smem + OFF_SMK);

    int tid = threadIdx.x, wid = tid >> 5, lane = tid & 31;
    int wm = (wid >> 2)*64, wn = (wid & 3)*32;
    int m0 = blockIdx.y*128, n0 = blockIdx.x*128;

    for (int i = tid; i < 512;  i += 256) s_bias[i] = bias[i];
    for (int i = tid; i < 1024; i += 256) s_a[i]    = a_vec[i];
    for (int i = tid; i < 2048; i += 256) s_sm[i]   = 0.f;
    if (tid < 16) s_mk[tid] = 0u;

    float d[4][4][4];
#pragma unroll
    for (int mi = 0; mi < 4; mi++)
#pragma unroll
        for (int ni = 0; ni < 4; ni++)
#pragma unroll
            for (int k = 0; k < 4; k++) d[mi][ni][k] = 0.f;

    const __nv_bfloat16* Abase  = g_Ah  + (size_t)m0*IN_DIM;
    const __nv_bfloat16* Albase = g_Al  + (size_t)m0*IN_DIM;
    const __nv_bfloat16* Bbase  = g_Bth + (size_t)n0*IN_DIM;
    const __nv_bfloat16* Blbase = g_Btl + (size_t)n0*IN_DIM;

#pragma unroll
    for (int c = 0; c < 2; c++){
        uint32_t st = sb + OFF_A + c*ST;
        load_tile32(st,          Abase  + c*32, tid);
        load_tile32(st +   TILE, Albase + c*32, tid);
        load_tile32(st + 2*TILE, Bbase  + c*32, tid);
        load_tile32(st + 3*TILE, Blbase + c*32, tid);
        asm volatile("cp.async.commit_group;" ::: "memory");
    }

    // CSC reorder: 512 edges per CTA, hidden behind prologue loads
    {
        int cta = blockIdx.y*4 + blockIdx.x;
#pragma unroll
        for (int r = 0; r < 2; r++){
            int e = cta*512 + r*256 + tid;
            if (e < NEDGES){
                int row = ei[e], col = ei[NEDGES + e];
                int pos = atomicAdd(&g_cur[col], 1);
                g_srow[pos] = row;
            }
        }
    }

    for (int c = 0; c < 8; c++){
        asm volatile("cp.async.wait_group 1;" ::: "memory");
        __syncthreads();
        int cn = c + 2;
        if (cn < 8){
            uint32_t st = sb + OFF_A + (cn % 3)*ST;
            load_tile32(st,          Abase  + cn*32, tid);
            load_tile32(st +   TILE, Albase + cn*32, tid);
            load_tile32(st + 2*TILE, Bbase  + cn*32, tid);
            load_tile32(st + 3*TILE, Blbase + cn*32, tid);
        }
        asm volatile("cp.async.commit_group;" ::: "memory");
        gemm_stage(sb + OFF_A + (c % 3)*ST, wm, wn, lane, d);
    }

    // -------- epilogue --------
    int h = (n0 + wn) >> 6;
    const float* aS = s_a + h*128;
    const float* aD = s_a + h*128 + 64;
    float accS[4][2], accD[4][2];
#pragma unroll
    for (int mi = 0; mi < 4; mi++){ accS[mi][0]=accS[mi][1]=accD[mi][0]=accD[mi][1]=0.f; }

#pragma unroll
    for (int mi = 0; mi < 4; mi++){
#pragma unroll
        for (int ni = 0; ni < 4; ni++){
            int C = wn + ni*8 + (lane & 3)*2;
            int o = C & 63;
            float b0 = s_bias[n0 + C], b1 = s_bias[n0 + C + 1];
#pragma unroll
            for (int rr = 0; rr < 2; rr++){
                float v0 = d[mi][ni][rr*2 + 0] + b0;
                float v1 = d[mi][ni][rr*2 + 1] + b1;
                int R = wm + mi*16 + (lane >> 2) + rr*8;
                int gm = m0 + R;
                if (gm < NNODES){
                    __half2 hv = __floats2half2_rn(v0, v1);
                    *reinterpret_cast<__half2*>(g_Wh16 + (size_t)gm*NH + n0 + C) = hv;
                }
                accS[mi][rr] += v0*aS[o] + v1*aS[o+1];
                accD[mi][rr] += v0*aD[o] + v1*aD[o+1];
            }
        }
    }
#pragma unroll
    for (int mi = 0; mi < 4; mi++)
#pragma unroll
        for (int rr = 0; rr < 2; rr++){
            float vs = accS[mi][rr], vd = accD[mi][rr];
            vs += __shfl_xor_sync(0xffffffffu, vs, 1);
            vs += __shfl_xor_sync(0xffffffffu, vs, 2);
            vd += __shfl_xor_sync(0xffffffffu, vd, 1);
            vd += __shfl_xor_sync(0xffffffffu, vd, 2);
            if ((lane & 3) == 0){
                int R = wm + mi*16 + (lane >> 2) + rr*8;
                atomicAdd(&s_sm[R*16 + h],     vs);
                atomicAdd(&s_sm[R*16 + 8 + h], vd);
            }
        }
    __syncthreads();
    int h0 = n0 >> 6;
    for (int i = tid; i < 512; i += 256){
        int r = i >> 2, jj = i & 3;
        int j = h0 + (jj & 1) + (jj >> 1)*8;
        int gm = m0 + r;
        if (gm < NNODES){
            float v = s_sm[r*16 + j];
            g_s[gm*16 + j] = v;
            atomicMax(&s_mk[j], fkey(v));
        }
    }
    __syncthreads();
    if (tid < 4){
        int j = h0 + (tid & 1) + (tid >> 1)*8;
        unsigned k = s_mk[j];
        if (k) atomicMax(&g_mkey[j], k);
    }
}

// ---------------- per-head Z (CSC order, warp per col) ----------------
__global__ __launch_bounds__(256) void k_Z(){
    __shared__ float sM[8];
    __shared__ float ssum[8];
    if (threadIdx.x < 8){
        float m = fdec(g_mkey[threadIdx.x]) + fdec(g_mkey[8 + threadIdx.x]);
        sM[threadIdx.x] = (m > 0.f) ? m : 0.01f*m;
        ssum[threadIdx.x] = 0.f;
    }
    __syncthreads();
    int warp = threadIdx.x >> 5, lane = threadIdx.x & 31;
    int hh = lane & 7, sub = lane >> 3;
    int c = blockIdx.x*8 + warp;
    float zacc = 0.f;
    if (c < NNODES){
        int p0 = g_colptr[c], p1 = g_colptr[c+1];
        if (p0 < p1){
            float sd = g_s[c*16 + 8 + hh];
            float Mh = sM[hh];
            for (int p = p0; p < p1; p += 4){
                int idx = p + sub;
                int rowv = g_srow[min(idx, p1-1)];
                float t = g_s[rowv*16 + hh] + sd;
                t = (t > 0.f) ? t : 0.01f*t;
                float w = __expf(t - Mh);
                if (idx < p1) zacc += w;
            }
        }
    }
    zacc += __shfl_xor_sync(0xffffffffu, zacc, 16);
    zacc += __shfl_xor_sync(0xffffffffu, zacc, 8);
    if (lane < 8) atomicAdd(&ssum[lane], zacc);
    __syncthreads();
    if (threadIdx.x < 8) atomicAdd(&g_Z[threadIdx.x], ssum[threadIdx.x]);
}

// ---------------- CSC scatter: warp per col, 4-edge unroll, coalesced RED ----------------
__global__ __launch_bounds__(256) void k_scatter(float* __restrict__ out){
    __shared__ float sc[8];
    __shared__ float sMs[8];
    if (threadIdx.x < 8){
        sc[threadIdx.x] = g_gate[threadIdx.x] / g_Z[threadIdx.x];
        float m = fdec(g_mkey[threadIdx.x]) + fdec(g_mkey[8 + threadIdx.x]);
        sMs[threadIdx.x] = (m > 0.f) ? m : 0.01f*m;
    }
    __syncthreads();
    int warp = threadIdx.x >> 5, lane = threadIdx.x & 31;
    int c = blockIdx.x*8 + warp;
    if (c >= NNODES) return;
    int p0 = g_colptr[c], p1 = g_colptr[c+1];
    if (p0 == p1) return;
    const __half* wp = g_Wh16 + (size_t)c*NH;
    float whv[16];
#pragma unroll
    for (int h = 0; h < 8; h++){
        whv[h]     = __half2float(wp[h*64 + lane]);
        whv[8 + h] = __half2float(wp[h*64 + 32 + lane]);
    }
    int hh = lane & 7, sub = lane >> 3;
    float sd = g_s[c*16 + 8 + hh];
    float ch = sc[hh];
    float Mh = sMs[hh];

    for (int p = p0; p < p1; p += 4){
        int idx = p + sub;
        int rowv = g_srow[min(idx, p1-1)];
        float t = g_s[rowv*16 + hh] + sd;
        t = (t > 0.f) ? t : 0.01f*t;
        float wv = (idx < p1) ? ch * __expf(t - Mh) : 0.f;

        float a0l = 0.f, a0h = 0.f, a1l = 0.f, a1h = 0.f;
        float a2l = 0.f, a2h = 0.f, a3l = 0.f, a3h = 0.f;
#pragma unroll
        for (int h = 0; h < 8; h++){
            float w0 = __shfl_sync(0xffffffffu, wv, h);
            float w1 = __shfl_sync(0xffffffffu, wv, 8 + h);
            float w2 = __shfl_sync(0xffffffffu, wv, 16 + h);
            float w3 = __shfl_sync(0xffffffffu, wv, 24 + h);
            a0l += w0*whv[h];  a0h += w0*whv[8+h];
            a1l += w1*whv[h];  a1h += w1*whv[8+h];
            a2l += w2*whv[h];  a2h += w2*whv[8+h];
            a3l += w3*whv[h];  a3h += w3*whv[8+h];
        }
        int r0 = __shfl_sync(0xffffffffu, rowv, 0);
        int r1 = __shfl_sync(0xffffffffu, rowv, 8);
        int r2 = __shfl_sync(0xffffffffu, rowv, 16);
        int r3 = __shfl_sync(0xffffffffu, rowv, 24);
        atomicAdd(out + (size_t)r0*64 + lane,      a0l);
        atomicAdd(out + (size_t)r0*64 + 32 + lane, a0h);
        if (p + 1 < p1){
            atomicAdd(out + (size_t)r1*64 + lane,      a1l);
            atomicAdd(out + (size_t)r1*64 + 32 + lane, a1h);
        }
        if (p + 2 < p1){
            atomicAdd(out + (size_t)r2*64 + lane,      a2l);
            atomicAdd(out + (size_t)r2*64 + 32 + lane, a2h);
        }
        if (p + 3 < p1){
            atomicAdd(out + (size_t)r3*64 + lane,      a3l);
            atomicAdd(out + (size_t)r3*64 + 32 + lane, a3h);
        }
    }
}

// ---------------- launch ----------------
extern "C" void kernel_launch(void* const* d_in, const int* in_sizes, int n_in,
                              void* d_out, int out_size){
    const float* x    = (const float*)d_in[0];
    const int*   ei   = (const int*)  d_in[1];
    const float* W    = (const float*)d_in[2];
    const float* b    = (const float*)d_in[3];
    const float* a    = (const float*)d_in[4];
    const float* gate = (const float*)d_in[5];
    float* out = (float*)d_out;

    cudaFuncSetAttribute(k_big, cudaFuncAttributeMaxDynamicSharedMemorySize, SMEM_BIG);

    k_setup<<<(NPAD*IN_DIM/4 + 255)/256, 256>>>(x, ei, W, gate, out);
    k_scan1<<<(NNODES + 255)/256, 256>>>();
    k_scan23<<<(NNODES + 255)/256, 256>>>();
    dim3 gg(4, NPAD/128);
    k_big<<<gg, 256, SMEM_BIG>>>(b, a, ei);
    k_Z<<<(NNODES + 7)/8, 256>>>();
    k_scatter<<<(NNODES + 7)/8, 256>>>(out);
}

// round 14
// speedup vs baseline: 1.2110x; 1.0027x over previous
#include <cuda_runtime.h>
#include <cuda_bf16.h>
#include <cuda_fp16.h>
#include <stdint.h>

#define NNODES 50000
#define NPAD   50048            // 391 * 128
#define NEDGES 800000
#define IN_DIM 256
#define HEADS  8
#define NH     512

// ---------------- device scratch ----------------
__device__ __align__(128) __nv_bfloat16 g_Ah[(size_t)NPAD*IN_DIM];
__device__ __align__(128) __nv_bfloat16 g_Al[(size_t)NPAD*IN_DIM];
__device__ __align__(128) __nv_bfloat16 g_Bth[NH*IN_DIM];
__device__ __align__(128) __nv_bfloat16 g_Btl[NH*IN_DIM];
__device__ __align__(128) __half g_Wh16[(size_t)NNODES*NH];   // 51.2 MB (fp16 Wh)
__device__ __align__(16)  float g_s[NNODES*16];
__device__ unsigned g_mkey[16];
__device__ float g_Z[HEADS];
__device__ float g_gate[HEADS];
__device__ int g_cnt[NNODES];          // zeroed by scan1 for next run
__device__ int g_colptr[NNODES+1];
__device__ int g_cur[NNODES];
__device__ int g_bsum[256];
__device__ int g_srow[NEDGES];

// ---------------- helpers ----------------
__device__ __forceinline__ unsigned fkey(float f){
    unsigned b = __float_as_uint(f);
    return (b & 0x80000000u) ? ~b : (b | 0x80000000u);
}
__device__ __forceinline__ float fdec(unsigned k){
    return (k & 0x80000000u) ? __uint_as_float(k ^ 0x80000000u) : __uint_as_float(~k);
}
__device__ __forceinline__ uint32_t s2u(const void* p){
    return (uint32_t)__cvta_generic_to_shared(p);
}
__device__ __forceinline__ void cpa16(uint32_t dst, const void* src){
    asm volatile("cp.async.cg.shared.global [%0], [%1], 16;" :: "r"(dst), "l"(src));
}
__device__ __forceinline__ void ldsm4(uint32_t* r, uint32_t addr){
    asm volatile("ldmatrix.sync.aligned.m8n8.x4.shared.b16 {%0,%1,%2,%3}, [%4];"
        : "=r"(r[0]), "=r"(r[1]), "=r"(r[2]), "=r"(r[3]) : "r"(addr));
}
__device__ __forceinline__ void mma_bf16(float* d, const uint32_t* a, uint32_t b0, uint32_t b1){
    asm volatile("mma.sync.aligned.m16n8k16.row.col.f32.bf16.bf16.f32 "
        "{%0,%1,%2,%3},{%4,%5,%6,%7},{%8,%9},{%0,%1,%2,%3};"
        : "+f"(d[0]), "+f"(d[1]), "+f"(d[2]), "+f"(d[3])
        : "r"(a[0]), "r"(a[1]), "r"(a[2]), "r"(a[3]), "r"(b0), "r"(b1));
}
// packed f32x2 helpers
__device__ __forceinline__ unsigned long long dup2(float a){
    unsigned long long r;
    asm("mov.b64 %0, {%1, %1};" : "=l"(r) : "r"(__float_as_uint(a)));
    return r;
}
__device__ __forceinline__ unsigned long long pack2(float lo, float hi){
    unsigned long long r;
    asm("mov.b64 %0, {%1, %2};" : "=l"(r) : "r"(__float_as_uint(lo)), "r"(__float_as_uint(hi)));
    return r;
}
__device__ __forceinline__ void fma2(unsigned long long &acc, unsigned long long a, unsigned long long b){
    asm("fma.rn.f32x2 %0, %1, %2, %0;" : "+l"(acc) : "l"(a), "l"(b));
}
__device__ __forceinline__ void unpack2(unsigned long long v, float &lo, float &hi){
    unsigned l, h;
    asm("mov.b64 {%0, %1}, %2;" : "=r"(l), "=r"(h) : "l"(v));
    lo = __uint_as_float(l); hi = __uint_as_float(h);
}

// ---------------- fused setup ----------------
__global__ void k_setup(const float* __restrict__ x, const int* __restrict__ ei,
                        const float* __restrict__ W, const float* __restrict__ gate,
                        float* __restrict__ out){
    int tid = blockIdx.x*blockDim.x + threadIdx.x;
    if (tid < 8)  g_Z[tid] = 0.f;
    if (tid < 16) g_mkey[tid] = 0u;
    if (tid == 0){
        float m = -1e30f;
        for (int h = 0; h < HEADS; h++) m = fmaxf(m, gate[h]);
        float ex[HEADS]; float z = 0.f;
        for (int h = 0; h < HEADS; h++){ ex[h] = __expf(gate[h]-m); z += ex[h]; }
        for (int h = 0; h < HEADS; h++) g_gate[h] = ex[h]/z;
    }
    if (tid < NNODES*16)
        reinterpret_cast<float4*>(out)[tid] = make_float4(0.f,0.f,0.f,0.f);
    if (tid < NEDGES) atomicAdd(&g_cnt[ei[NEDGES + tid]], 1);
    if (tid < NH*IN_DIM){
        int n = tid >> 8, d = tid & 255;
        int h = n >> 6, o = n & 63;
        float v = W[(size_t)h*IN_DIM*64 + d*64 + o];
        __nv_bfloat16 hb = __float2bfloat16(v);
        __nv_bfloat16 lb = __float2bfloat16(v - __bfloat162float(hb));
        g_Bth[tid] = hb;
        g_Btl[tid] = lb;
    }
    if (tid < NPAD*IN_DIM/4){
        int base = tid*4;
        int row = base / IN_DIM;
        float4 v = make_float4(0.f,0.f,0.f,0.f);
        if (row < NNODES) v = *reinterpret_cast<const float4*>(x + base);
        float vv[4] = {v.x, v.y, v.z, v.w};
        unsigned short hb[4], lb[4];
#pragma unroll
        for (int j = 0; j < 4; j++){
            __nv_bfloat16 h = __float2bfloat16(vv[j]);
            __nv_bfloat16 l = __float2bfloat16(vv[j] - __bfloat162float(h));
            hb[j] = __bfloat16_as_ushort(h);
            lb[j] = __bfloat16_as_ushort(l);
        }
        uint2 ph = make_uint2((unsigned)hb[0] | ((unsigned)hb[1]<<16),
                              (unsigned)hb[2] | ((unsigned)hb[3]<<16));
        uint2 pl = make_uint2((unsigned)lb[0] | ((unsigned)lb[1]<<16),
                              (unsigned)lb[2] | ((unsigned)lb[3]<<16));
        *reinterpret_cast<uint2*>(reinterpret_cast<char*>(g_Ah) + (size_t)base*2) = ph;
        *reinterpret_cast<uint2*>(reinterpret_cast<char*>(g_Al) + (size_t)base*2) = pl;
    }
}

// ---------------- CSC scans ----------------
__global__ void k_scan1(){
    __shared__ int sd[256];
    int tid = threadIdx.x;
    int i = blockIdx.x*256 + tid;
    int v = (i < NNODES) ? g_cnt[i] : 0;
    if (i < NNODES) g_cnt[i] = 0;
    sd[tid] = v; __syncthreads();
    for (int off = 1; off < 256; off <<= 1){
        int t = (tid >= off) ? sd[tid - off] : 0;
        __syncthreads();
        sd[tid] += t;
        __syncthreads();
    }
    if (i < NNODES) g_colptr[i] = sd[tid] - v;
    if (tid == 255) g_bsum[blockIdx.x] = sd[255];
}
__global__ void k_scan23(){
    __shared__ int sd[256];
    __shared__ int s_off;
    int tid = threadIdx.x;
    const int nb = (NNODES + 255)/256;
    int v = (tid < nb) ? g_bsum[tid] : 0;
    sd[tid] = v; __syncthreads();
    for (int off = 1; off < 256; off <<= 1){
        int t = (tid >= off) ? sd[tid - off] : 0;
        __syncthreads();
        sd[tid] += t;
        __syncthreads();
    }
    if (tid == (int)blockIdx.x) s_off = sd[tid] - v;
    __syncthreads();
    int i = blockIdx.x*256 + tid;
    if (i < NNODES){
        int p = g_colptr[i] + s_off;
        g_colptr[i] = p;
        g_cur[i]    = p;
    }
    if (blockIdx.x == 0 && tid == 0) g_colptr[NNODES] = NEDGES;
}

// ---------------- big kernel: fused 3-product stage loop (HMMA ceiling) ----------------
#define TILE     8192
#define ST       32768
#define OFF_A    0
#define OFF_BIAS 98304
#define OFF_SA   100352
#define OFF_SSM  104448
#define OFF_SMK  112640
#define SMEM_BIG 112704

__device__ __forceinline__ void load_tile32(uint32_t dstbase, const __nv_bfloat16* __restrict__ src,
                                            int tid){
#pragma unroll
    for (int i = 0; i < 2; i++){
        int idx = tid + i*256;
        int r = idx >> 2, qq = idx & 3;
        uint32_t off = (uint32_t)(r*64 + ((qq ^ ((r >> 1) & 3)) << 4));
        cpa16(dstbase + off, src + (size_t)r*IN_DIM + qq*8);
    }
}

__device__ __forceinline__ void gemm_stage(uint32_t sb_st, int wm, int wn, int lane,
                                           float d[4][4][4]){
    int lr = lane & 15;
    int qh = lane >> 4;
    uint32_t arow[4], brow[2];
    int asw[4], bsw[2];
#pragma unroll
    for (int mi = 0; mi < 4; mi++){
        int row = wm + mi*16 + lr;
        arow[mi] = sb_st + row*64;
        asw[mi]  = (row >> 1) & 3;
    }
#pragma unroll
    for (int bi = 0; bi < 2; bi++){
        int row = wn + bi*16 + lr;
        brow[bi] = sb_st + 2*TILE + row*64;
        bsw[bi]  = (row >> 1) & 3;
    }
#pragma unroll
    for (int ks = 0; ks < 2; ks++){
        int q = ks*2 + qh;
        uint32_t af[4][4], bfh[2][4], bfl[2][4];
#pragma unroll
        for (int mi = 0; mi < 4; mi++)
            ldsm4(af[mi], arow[mi] + ((q ^ asw[mi]) << 4));
#pragma unroll
        for (int bi = 0; bi < 2; bi++){
            uint32_t boff = ((q ^ bsw[bi]) << 4);
            ldsm4(bfh[bi], brow[bi] + boff);
            ldsm4(bfl[bi], brow[bi] + TILE + boff);
        }
#pragma unroll
        for (int mi = 0; mi < 4; mi++)
#pragma unroll
            for (int ni = 0; ni < 4; ni++){
                int bi = ni >> 1, sub = ni & 1;
                mma_bf16(d[mi][ni], af[mi], bfh[bi][sub], bfh[bi][sub + 2]);
                mma_bf16(d[mi][ni], af[mi], bfl[bi][sub], bfl[bi][sub + 2]);
            }
#pragma unroll
        for (int mi = 0; mi < 4; mi++)
            ldsm4(af[mi], arow[mi] + TILE + ((q ^ asw[mi]) << 4));
#pragma unroll
        for (int mi = 0; mi < 4; mi++)
#pragma unroll
            for (int ni = 0; ni < 4; ni++){
                int bi = ni >> 1, sub = ni & 1;
                mma_bf16(d[mi][ni], af[mi], bfh[bi][sub], bfh[bi][sub + 2]);
            }
    }
}

// grid = (4, 391)
__global__ __launch_bounds__(256,2) void k_big(const float* __restrict__ bias,
                                               const float* __restrict__ a_vec,
                                               const int* __restrict__ ei){
    extern __shared__ char smem[];
    uint32_t sb = s2u(smem);
    float*    s_bias = (float*)(smem + OFF_BIAS);
    float*    s_a    = (float*)(smem + OFF_SA);
    float*    s_sm   = (float*)(smem + OFF_SSM);
    unsigned* s_mk   = (unsigned*)(smem + OFF_SMK);

    int tid = threadIdx.x, wid = tid >> 5, lane = tid & 31;
    int wm = (wid >> 2)*64, wn = (wid & 3)*32;
    int m0 = blockIdx.y*128, n0 = blockIdx.x*128;

    for (int i = tid; i < 512;  i += 256) s_bias[i] = bias[i];
    for (int i = tid; i < 1024; i += 256) s_a[i]    = a_vec[i];
    for (int i = tid; i < 2048; i += 256) s_sm[i]   = 0.f;
    if (tid < 16) s_mk[tid] = 0u;

    float d[4][4][4];
#pragma unroll
    for (int mi = 0; mi < 4; mi++)
#pragma unroll
        for (int ni = 0; ni < 4; ni++)
#pragma unroll
            for (int k = 0; k < 4; k++) d[mi][ni][k] = 0.f;

    const __nv_bfloat16* Abase  = g_Ah  + (size_t)m0*IN_DIM;
    const __nv_bfloat16* Albase = g_Al  + (size_t)m0*IN_DIM;
    const __nv_bfloat16* Bbase  = g_Bth + (size_t)n0*IN_DIM;
    const __nv_bfloat16* Blbase = g_Btl + (size_t)n0*IN_DIM;

#pragma unroll
    for (int c = 0; c < 2; c++){
        uint32_t st = sb + OFF_A + c*ST;
        load_tile32(st,          Abase  + c*32, tid);
        load_tile32(st +   TILE, Albase + c*32, tid);
        load_tile32(st + 2*TILE, Bbase  + c*32, tid);
        load_tile32(st + 3*TILE, Blbase + c*32, tid);
        asm volatile("cp.async.commit_group;" ::: "memory");
    }

    // CSC reorder: 512 edges per CTA, hidden behind prologue loads
    {
        int cta = blockIdx.y*4 + blockIdx.x;
#pragma unroll
        for (int r = 0; r < 2; r++){
            int e = cta*512 + r*256 + tid;
            if (e < NEDGES){
                int row = ei[e], col = ei[NEDGES + e];
                int pos = atomicAdd(&g_cur[col], 1);
                g_srow[pos] = row;
            }
        }
    }

    for (int c = 0; c < 8; c++){
        asm volatile("cp.async.wait_group 1;" ::: "memory");
        __syncthreads();
        int cn = c + 2;
        if (cn < 8){
            uint32_t st = sb + OFF_A + (cn % 3)*ST;
            load_tile32(st,          Abase  + cn*32, tid);
            load_tile32(st +   TILE, Albase + cn*32, tid);
            load_tile32(st + 2*TILE, Bbase  + cn*32, tid);
            load_tile32(st + 3*TILE, Blbase + cn*32, tid);
        }
        asm volatile("cp.async.commit_group;" ::: "memory");
        gemm_stage(sb + OFF_A + (c % 3)*ST, wm, wn, lane, d);
    }

    // -------- epilogue --------
    int h = (n0 + wn) >> 6;
    const float* aS = s_a + h*128;
    const float* aD = s_a + h*128 + 64;
    float accS[4][2], accD[4][2];
#pragma unroll
    for (int mi = 0; mi < 4; mi++){ accS[mi][0]=accS[mi][1]=accD[mi][0]=accD[mi][1]=0.f; }

#pragma unroll
    for (int mi = 0; mi < 4; mi++){
#pragma unroll
        for (int ni = 0; ni < 4; ni++){
            int C = wn + ni*8 + (lane & 3)*2;
            int o = C & 63;
            float b0 = s_bias[n0 + C], b1 = s_bias[n0 + C + 1];
#pragma unroll
            for (int rr = 0; rr < 2; rr++){
                float v0 = d[mi][ni][rr*2 + 0] + b0;
                float v1 = d[mi][ni][rr*2 + 1] + b1;
                int R = wm + mi*16 + (lane >> 2) + rr*8;
                int gm = m0 + R;
                if (gm < NNODES){
                    __half2 hv = __floats2half2_rn(v0, v1);
                    *reinterpret_cast<__half2*>(g_Wh16 + (size_t)gm*NH + n0 + C) = hv;
                }
                accS[mi][rr] += v0*aS[o] + v1*aS[o+1];
                accD[mi][rr] += v0*aD[o] + v1*aD[o+1];
            }
        }
    }
#pragma unroll
    for (int mi = 0; mi < 4; mi++)
#pragma unroll
        for (int rr = 0; rr < 2; rr++){
            float vs = accS[mi][rr], vd = accD[mi][rr];
            vs += __shfl_xor_sync(0xffffffffu, vs, 1);
            vs += __shfl_xor_sync(0xffffffffu, vs, 2);
            vd += __shfl_xor_sync(0xffffffffu, vd, 1);
            vd += __shfl_xor_sync(0xffffffffu, vd, 2);
            if ((lane & 3) == 0){
                int R = wm + mi*16 + (lane >> 2) + rr*8;
                atomicAdd(&s_sm[R*16 + h],     vs);
                atomicAdd(&s_sm[R*16 + 8 + h], vd);
            }
        }
    __syncthreads();
    int h0 = n0 >> 6;
    for (int i = tid; i < 512; i += 256){
        int r = i >> 2, jj = i & 3;
        int j = h0 + (jj & 1) + (jj >> 1)*8;
        int gm = m0 + r;
        if (gm < NNODES){
            float v = s_sm[r*16 + j];
            g_s[gm*16 + j] = v;
            atomicMax(&s_mk[j], fkey(v));
        }
    }
    __syncthreads();
    if (tid < 4){
        int j = h0 + (tid & 1) + (tid >> 1)*8;
        unsigned k = s_mk[j];
        if (k) atomicMax(&g_mkey[j], k);
    }
}

// ---------------- per-head Z (CSC order, warp per col) ----------------
__global__ __launch_bounds__(256) void k_Z(){
    __shared__ float sM[8];
    __shared__ float ssum[8];
    if (threadIdx.x < 8){
        float m = fdec(g_mkey[threadIdx.x]) + fdec(g_mkey[8 + threadIdx.x]);
        sM[threadIdx.x] = (m > 0.f) ? m : 0.01f*m;
        ssum[threadIdx.x] = 0.f;
    }
    __syncthreads();
    int warp = threadIdx.x >> 5, lane = threadIdx.x & 31;
    int hh = lane & 7, sub = lane >> 3;
    int c = blockIdx.x*8 + warp;
    float zacc = 0.f;
    if (c < NNODES){
        int p0 = g_colptr[c], p1 = g_colptr[c+1];
        if (p0 < p1){
            float sd = g_s[c*16 + 8 + hh];
            float Mh = sM[hh];
            for (int p = p0; p < p1; p += 4){
                int idx = p + sub;
                int rowv = g_srow[min(idx, p1-1)];
                float t = g_s[rowv*16 + hh] + sd;
                t = (t > 0.f) ? t : 0.01f*t;
                float w = __expf(t - Mh);
                if (idx < p1) zacc += w;
            }
        }
    }
    zacc += __shfl_xor_sync(0xffffffffu, zacc, 16);
    zacc += __shfl_xor_sync(0xffffffffu, zacc, 8);
    if (lane < 8) atomicAdd(&ssum[lane], zacc);
    __syncthreads();
    if (threadIdx.x < 8) atomicAdd(&g_Z[threadIdx.x], ssum[threadIdx.x]);
}

// ---------------- CSC scatter: warp per col, 4-edge unroll, packed f32x2 FMA ----------------
__global__ __launch_bounds__(256) void k_scatter(float* __restrict__ out){
    __shared__ float sc[8];
    __shared__ float sMs[8];
    if (threadIdx.x < 8){
        sc[threadIdx.x] = g_gate[threadIdx.x] / g_Z[threadIdx.x];
        float m = fdec(g_mkey[threadIdx.x]) + fdec(g_mkey[8 + threadIdx.x]);
        sMs[threadIdx.x] = (m > 0.f) ? m : 0.01f*m;
    }
    __syncthreads();
    int warp = threadIdx.x >> 5, lane = threadIdx.x & 31;
    int c = blockIdx.x*8 + warp;
    if (c >= NNODES) return;
    int p0 = g_colptr[c], p1 = g_colptr[c+1];
    if (p0 == p1) return;
    const __half* wp = g_Wh16 + (size_t)c*NH;
    // lane owns cols lane (A) and 32+lane (B); Wh values pre-duplicated for f32x2
    unsigned long long whA[8], whB[8];
#pragma unroll
    for (int h = 0; h < 8; h++){
        whA[h] = dup2(__half2float(wp[h*64 + lane]));
        whB[h] = dup2(__half2float(wp[h*64 + 32 + lane]));
    }
    int hh = lane & 7, sub = lane >> 3;
    float sd = g_s[c*16 + 8 + hh];
    float ch = sc[hh];
    float Mh = sMs[hh];

    for (int p = p0; p < p1; p += 4){
        int idx = p + sub;
        int rowv = g_srow[min(idx, p1-1)];
        float t = g_s[rowv*16 + hh] + sd;
        t = (t > 0.f) ? t : 0.01f*t;
        float wv = (idx < p1) ? ch * __expf(t - Mh) : 0.f;

        unsigned long long acc01A = 0ull, acc23A = 0ull;
        unsigned long long acc01B = 0ull, acc23B = 0ull;
#pragma unroll
        for (int h = 0; h < 8; h++){
            float w0 = __shfl_sync(0xffffffffu, wv, h);
            float w1 = __shfl_sync(0xffffffffu, wv, 8 + h);
            float w2 = __shfl_sync(0xffffffffu, wv, 16 + h);
            float w3 = __shfl_sync(0xffffffffu, wv, 24 + h);
            unsigned long long w01 = pack2(w0, w1);
            unsigned long long w23 = pack2(w2, w3);
            fma2(acc01A, w01, whA[h]);
            fma2(acc23A, w23, whA[h]);
            fma2(acc01B, w01, whB[h]);
            fma2(acc23B, w23, whB[h]);
        }
        float a0A, a1A, a2A, a3A, a0B, a1B, a2B, a3B;
        unpack2(acc01A, a0A, a1A);
        unpack2(acc23A, a2A, a3A);
        unpack2(acc01B, a0B, a1B);
        unpack2(acc23B, a2B, a3B);
        int r0 = __shfl_sync(0xffffffffu, rowv, 0);
        int r1 = __shfl_sync(0xffffffffu, rowv, 8);
        int r2 = __shfl_sync(0xffffffffu, rowv, 16);
        int r3 = __shfl_sync(0xffffffffu, rowv, 24);
        atomicAdd(out + (size_t)r0*64 + lane,      a0A);
        atomicAdd(out + (size_t)r0*64 + 32 + lane, a0B);
        if (p + 1 < p1){
            atomicAdd(out + (size_t)r1*64 + lane,      a1A);
            atomicAdd(out + (size_t)r1*64 + 32 + lane, a1B);
        }
        if (p + 2 < p1){
            atomicAdd(out + (size_t)r2*64 + lane,      a2A);
            atomicAdd(out + (size_t)r2*64 + 32 + lane, a2B);
        }
        if (p + 3 < p1){
            atomicAdd(out + (size_t)r3*64 + lane,      a3A);
            atomicAdd(out + (size_t)r3*64 + 32 + lane, a3B);
        }
    }
}

// ---------------- launch ----------------
extern "C" void kernel_launch(void* const* d_in, const int* in_sizes, int n_in,
                              void* d_out, int out_size){
    const float* x    = (const float*)d_in[0];
    const int*   ei   = (const int*)  d_in[1];
    const float* W    = (const float*)d_in[2];
    const float* b    = (const float*)d_in[3];
    const float* a    = (const float*)d_in[4];
    const float* gate = (const float*)d_in[5];
    float* out = (float*)d_out;

    cudaFuncSetAttribute(k_big, cudaFuncAttributeMaxDynamicSharedMemorySize, SMEM_BIG);

    k_setup<<<(NPAD*IN_DIM/4 + 255)/256, 256>>>(x, ei, W, gate, out);
    k_scan1<<<(NNODES + 255)/256, 256>>>();
    k_scan23<<<(NNODES + 255)/256, 256>>>();
    dim3 gg(4, NPAD/128);
    k_big<<<gg, 256, SMEM_BIG>>>(b, a, ei);
    k_Z<<<(NNODES + 7)/8, 256>>>();
    k_scatter<<<(NNODES + 7)/8, 256>>>(out);
}

// round 15
// speedup vs baseline: 1.2288x; 1.0148x over previous
#include <cuda_runtime.h>
#include <cuda_bf16.h>
#include <cuda_fp16.h>
#include <stdint.h>

#define NNODES 50000
#define NPAD   50048            // 391 * 128
#define NEDGES 800000
#define IN_DIM 256
#define HEADS  8
#define NH     512

// ---------------- device scratch ----------------
__device__ __align__(128) __nv_bfloat16 g_Ah[(size_t)NPAD*IN_DIM];
__device__ __align__(128) __nv_bfloat16 g_Al[(size_t)NPAD*IN_DIM];
__device__ __align__(128) __nv_bfloat16 g_Bth[NH*IN_DIM];
__device__ __align__(128) __nv_bfloat16 g_Btl[NH*IN_DIM];
__device__ __align__(128) __half g_Wh16[(size_t)NNODES*NH];   // 51.2 MB (fp16 Wh)
__device__ __align__(16)  float g_s[NNODES*16];
__device__ unsigned g_mkey[16];
__device__ float g_Z[HEADS];
__device__ float g_gate[HEADS];
__device__ int g_cnt[NNODES];          // zeroed by scan1 for next run
__device__ int g_colptr[NNODES+1];
__device__ int g_cur[NNODES];
__device__ int g_bsum[256];
__device__ int g_srow[NEDGES];

// ---------------- helpers ----------------
__device__ __forceinline__ unsigned fkey(float f){
    unsigned b = __float_as_uint(f);
    return (b & 0x80000000u) ? ~b : (b | 0x80000000u);
}
__device__ __forceinline__ float fdec(unsigned k){
    return (k & 0x80000000u) ? __uint_as_float(k ^ 0x80000000u) : __uint_as_float(~k);
}
__device__ __forceinline__ uint32_t s2u(const void* p){
    return (uint32_t)__cvta_generic_to_shared(p);
}
__device__ __forceinline__ void cpa16(uint32_t dst, const void* src){
    asm volatile("cp.async.cg.shared.global [%0], [%1], 16;" :: "r"(dst), "l"(src));
}
__device__ __forceinline__ void ldsm4(uint32_t* r, uint32_t addr){
    asm volatile("ldmatrix.sync.aligned.m8n8.x4.shared.b16 {%0,%1,%2,%3}, [%4];"
        : "=r"(r[0]), "=r"(r[1]), "=r"(r[2]), "=r"(r[3]) : "r"(addr));
}
__device__ __forceinline__ void mma_bf16(float* d, const uint32_t* a, uint32_t b0, uint32_t b1){
    asm volatile("mma.sync.aligned.m16n8k16.row.col.f32.bf16.bf16.f32 "
        "{%0,%1,%2,%3},{%4,%5,%6,%7},{%8,%9},{%0,%1,%2,%3};"
        : "+f"(d[0]), "+f"(d[1]), "+f"(d[2]), "+f"(d[3])
        : "r"(a[0]), "r"(a[1]), "r"(a[2]), "r"(a[3]), "r"(b0), "r"(b1));
}

// ---------------- fused setup ----------------
__global__ void k_setup(const float* __restrict__ x, const int* __restrict__ ei,
                        const float* __restrict__ W, const float* __restrict__ gate,
                        float* __restrict__ out){
    int tid = blockIdx.x*blockDim.x + threadIdx.x;
    if (tid < 8)  g_Z[tid] = 0.f;
    if (tid < 16) g_mkey[tid] = 0u;
    if (tid == 0){
        float m = -1e30f;
        for (int h = 0; h < HEADS; h++) m = fmaxf(m, gate[h]);
        float ex[HEADS]; float z = 0.f;
        for (int h = 0; h < HEADS; h++){ ex[h] = __expf(gate[h]-m); z += ex[h]; }
        for (int h = 0; h < HEADS; h++) g_gate[h] = ex[h]/z;
    }
    if (tid < NNODES*16)
        reinterpret_cast<float4*>(out)[tid] = make_float4(0.f,0.f,0.f,0.f);
    if (tid < NEDGES) atomicAdd(&g_cnt[ei[NEDGES + tid]], 1);
    if (tid < NH*IN_DIM){
        int n = tid >> 8, d = tid & 255;
        int h = n >> 6, o = n & 63;
        float v = W[(size_t)h*IN_DIM*64 + d*64 + o];
        __nv_bfloat16 hb = __float2bfloat16(v);
        __nv_bfloat16 lb = __float2bfloat16(v - __bfloat162float(hb));
        g_Bth[tid] = hb;
        g_Btl[tid] = lb;
    }
    if (tid < NPAD*IN_DIM/4){
        int base = tid*4;
        int row = base / IN_DIM;
        float4 v = make_float4(0.f,0.f,0.f,0.f);
        if (row < NNODES) v = *reinterpret_cast<const float4*>(x + base);
        float vv[4] = {v.x, v.y, v.z, v.w};
        unsigned short hb[4], lb[4];
#pragma unroll
        for (int j = 0; j < 4; j++){
            __nv_bfloat16 h = __float2bfloat16(vv[j]);
            __nv_bfloat16 l = __float2bfloat16(vv[j] - __bfloat162float(h));
            hb[j] = __bfloat16_as_ushort(h);
            lb[j] = __bfloat16_as_ushort(l);
        }
        uint2 ph = make_uint2((unsigned)hb[0] | ((unsigned)hb[1]<<16),
                              (unsigned)hb[2] | ((unsigned)hb[3]<<16));
        uint2 pl = make_uint2((unsigned)lb[0] | ((unsigned)lb[1]<<16),
                              (unsigned)lb[2] | ((unsigned)lb[3]<<16));
        *reinterpret_cast<uint2*>(reinterpret_cast<char*>(g_Ah) + (size_t)base*2) = ph;
        *reinterpret_cast<uint2*>(reinterpret_cast<char*>(g_Al) + (size_t)base*2) = pl;
    }
}

// ---------------- CSC scans ----------------
__global__ void k_scan1(){
    __shared__ int sd[256];
    int tid = threadIdx.x;
    int i = blockIdx.x*256 + tid;
    int v = (i < NNODES) ? g_cnt[i] : 0;
    if (i < NNODES) g_cnt[i] = 0;
    sd[tid] = v; __syncthreads();
    for (int off = 1; off < 256; off <<= 1){
        int t = (tid >= off) ? sd[tid - off] : 0;
        __syncthreads();
        sd[tid] += t;
        __syncthreads();
    }
    if (i < NNODES) g_colptr[i] = sd[tid] - v;
    if (tid == 255) g_bsum[blockIdx.x] = sd[255];
}
__global__ void k_scan23(){
    __shared__ int sd[256];
    __shared__ int s_off;
    int tid = threadIdx.x;
    const int nb = (NNODES + 255)/256;
    int v = (tid < nb) ? g_bsum[tid] : 0;
    sd[tid] = v; __syncthreads();
    for (int off = 1; off < 256; off <<= 1){
        int t = (tid >= off) ? sd[tid - off] : 0;
        __syncthreads();
        sd[tid] += t;
        __syncthreads();
    }
    if (tid == (int)blockIdx.x) s_off = sd[tid] - v;
    __syncthreads();
    int i = blockIdx.x*256 + tid;
    if (i < NNODES){
        int p = g_colptr[i] + s_off;
        g_colptr[i] = p;
        g_cur[i]    = p;
    }
    if (blockIdx.x == 0 && tid == 0) g_colptr[NNODES] = NEDGES;
}

// ---------------- big kernel: 512 thr, 16 warps x 32x32 tiles, 3-stage, aux overlay ----------------
#define TILE     8192
#define ST       32768                  // stage = Ah,Al,Bh,Bl tiles (128x32 bf16 each)
#define SMEM_BIG 98304                  // 3 stages; aux overlaid in stage 0 post-mainloop

__device__ __forceinline__ void load_tile32(uint32_t dstbase, const __nv_bfloat16* __restrict__ src,
                                            int tid){
    // 512 threads: one 16B transfer each (128 rows x 4 chunks)
    int r = tid >> 2, qq = tid & 3;
    uint32_t off = (uint32_t)(r*64 + ((qq ^ ((r >> 1) & 3)) << 4));
    cpa16(dstbase + off, src + (size_t)r*IN_DIM + qq*8);
}

// all 3 split products from one stage; warp tile 32x32 (mi 0..1, ni 0..3)
__device__ __forceinline__ void gemm_stage(uint32_t sb_st, int wm, int wn, int lane,
                                           float d[2][4][4]){
    int lr = lane & 15;
    int qh = lane >> 4;
    uint32_t arow[2], brow[2];
    int asw[2], bsw[2];
#pragma unroll
    for (int mi = 0; mi < 2; mi++){
        int row = wm + mi*16 + lr;
        arow[mi] = sb_st + row*64;
        asw[mi]  = (row >> 1) & 3;
    }
#pragma unroll
    for (int bi = 0; bi < 2; bi++){
        int row = wn + bi*16 + lr;
        brow[bi] = sb_st + 2*TILE + row*64;
        bsw[bi]  = (row >> 1) & 3;
    }
#pragma unroll
    for (int ks = 0; ks < 2; ks++){
        int q = ks*2 + qh;
        uint32_t af[2][4], bfh[2][4], bfl[2][4];
#pragma unroll
        for (int mi = 0; mi < 2; mi++)
            ldsm4(af[mi], arow[mi] + ((q ^ asw[mi]) << 4));
#pragma unroll
        for (int bi = 0; bi < 2; bi++){
            uint32_t boff = ((q ^ bsw[bi]) << 4);
            ldsm4(bfh[bi], brow[bi] + boff);
            ldsm4(bfl[bi], brow[bi] + TILE + boff);
        }
#pragma unroll
        for (int mi = 0; mi < 2; mi++)
#pragma unroll
            for (int ni = 0; ni < 4; ni++){
                int bi = ni >> 1, sub = ni & 1;
                mma_bf16(d[mi][ni], af[mi], bfh[bi][sub], bfh[bi][sub + 2]);
                mma_bf16(d[mi][ni], af[mi], bfl[bi][sub], bfl[bi][sub + 2]);
            }
#pragma unroll
        for (int mi = 0; mi < 2; mi++)
            ldsm4(af[mi], arow[mi] + TILE + ((q ^ asw[mi]) << 4));
#pragma unroll
        for (int mi = 0; mi < 2; mi++)
#pragma unroll
            for (int ni = 0; ni < 4; ni++){
                int bi = ni >> 1, sub = ni & 1;
                mma_bf16(d[mi][ni], af[mi], bfh[bi][sub], bfh[bi][sub + 2]);
            }
    }
}

// grid = (4, 391), 512 threads
__global__ __launch_bounds__(512,2) void k_big(const float* __restrict__ bias,
                                               const float* __restrict__ a_vec,
                                               const int* __restrict__ ei){
    extern __shared__ char smem[];
    uint32_t sb = s2u(smem);

    int tid = threadIdx.x, wid = tid >> 5, lane = tid & 31;
    int wm = (wid >> 2)*32, wn = (wid & 3)*32;     // 4x4 warp grid of 32x32 tiles
    int m0 = blockIdx.y*128, n0 = blockIdx.x*128;

    float d[2][4][4];
#pragma unroll
    for (int mi = 0; mi < 2; mi++)
#pragma unroll
        for (int ni = 0; ni < 4; ni++)
#pragma unroll
            for (int k = 0; k < 4; k++) d[mi][ni][k] = 0.f;

    const __nv_bfloat16* Abase  = g_Ah  + (size_t)m0*IN_DIM;
    const __nv_bfloat16* Albase = g_Al  + (size_t)m0*IN_DIM;
    const __nv_bfloat16* Bbase  = g_Bth + (size_t)n0*IN_DIM;
    const __nv_bfloat16* Blbase = g_Btl + (size_t)n0*IN_DIM;

    // prologue: stages for chunks 0,1
#pragma unroll
    for (int c = 0; c < 2; c++){
        uint32_t st = sb + c*ST;
        load_tile32(st,          Abase  + c*32, tid);
        load_tile32(st +   TILE, Albase + c*32, tid);
        load_tile32(st + 2*TILE, Bbase  + c*32, tid);
        load_tile32(st + 3*TILE, Blbase + c*32, tid);
        asm volatile("cp.async.commit_group;" ::: "memory");
    }

    // CSC reorder: 512 edges per CTA (one per thread), hidden behind prologue loads
    {
        int e = (blockIdx.y*4 + blockIdx.x)*512 + tid;
        if (e < NEDGES){
            int row = ei[e], col = ei[NEDGES + e];
            int pos = atomicAdd(&g_cur[col], 1);
            g_srow[pos] = row;
        }
    }

    for (int c = 0; c < 8; c++){
        asm volatile("cp.async.wait_group 1;" ::: "memory");
        __syncthreads();
        int cn = c + 2;
        if (cn < 8){
            uint32_t st = sb + (cn % 3)*ST;
            load_tile32(st,          Abase  + cn*32, tid);
            load_tile32(st +   TILE, Albase + cn*32, tid);
            load_tile32(st + 2*TILE, Bbase  + cn*32, tid);
            load_tile32(st + 3*TILE, Blbase + cn*32, tid);
        }
        asm volatile("cp.async.commit_group;" ::: "memory");
        gemm_stage(sb + (c % 3)*ST, wm, wn, lane, d);
    }

    // -------- epilogue: aux overlaid into stage 0 (mainloop finished) --------
    asm volatile("cp.async.wait_group 0;" ::: "memory");
    __syncthreads();
    float*    s_bias = (float*)(smem);
    float*    s_a    = (float*)(smem + 2048);
    float*    s_sm   = (float*)(smem + 6144);
    unsigned* s_mk   = (unsigned*)(smem + 14336);
    if (tid < 512)  s_bias[tid] = bias[tid];
#pragma unroll
    for (int i = tid; i < 1024; i += 512) s_a[i] = a_vec[i];
#pragma unroll
    for (int i = tid; i < 2048; i += 512) s_sm[i] = 0.f;
    if (tid < 16) s_mk[tid] = 0u;
    __syncthreads();

    int h = (n0 + wn) >> 6;
    const float* aS = s_a + h*128;
    const float* aD = s_a + h*128 + 64;
    float accS[2][2], accD[2][2];
#pragma unroll
    for (int mi = 0; mi < 2; mi++){ accS[mi][0]=accS[mi][1]=accD[mi][0]=accD[mi][1]=0.f; }

#pragma unroll
    for (int mi = 0; mi < 2; mi++){
#pragma unroll
        for (int ni = 0; ni < 4; ni++){
            int C = wn + ni*8 + (lane & 3)*2;
            int o = C & 63;
            float b0 = s_bias[n0 + C], b1 = s_bias[n0 + C + 1];
#pragma unroll
            for (int rr = 0; rr < 2; rr++){
                float v0 = d[mi][ni][rr*2 + 0] + b0;
                float v1 = d[mi][ni][rr*2 + 1] + b1;
                int R = wm + mi*16 + (lane >> 2) + rr*8;
                int gm = m0 + R;
                if (gm < NNODES){
                    __half2 hv = __floats2half2_rn(v0, v1);
                    *reinterpret_cast<__half2*>(g_Wh16 + (size_t)gm*NH + n0 + C) = hv;
                }
                accS[mi][rr] += v0*aS[o] + v1*aS[o+1];
                accD[mi][rr] += v0*aD[o] + v1*aD[o+1];
            }
        }
    }
#pragma unroll
    for (int mi = 0; mi < 2; mi++)
#pragma unroll
        for (int rr = 0; rr < 2; rr++){
            float vs = accS[mi][rr], vd = accD[mi][rr];
            vs += __shfl_xor_sync(0xffffffffu, vs, 1);
            vs += __shfl_xor_sync(0xffffffffu, vs, 2);
            vd += __shfl_xor_sync(0xffffffffu, vd, 1);
            vd += __shfl_xor_sync(0xffffffffu, vd, 2);
            if ((lane & 3) == 0){
                int R = wm + mi*16 + (lane >> 2) + rr*8;
                atomicAdd(&s_sm[R*16 + h],     vs);
                atomicAdd(&s_sm[R*16 + 8 + h], vd);
            }
        }
    __syncthreads();
    int h0 = n0 >> 6;
    {
        int i = tid;          // 512 threads cover 128 rows x 4 (2 heads x src/dst)
        int r = i >> 2, jj = i & 3;
        int j = h0 + (jj & 1) + (jj >> 1)*8;
        int gm = m0 + r;
        if (gm < NNODES){
            float v = s_sm[r*16 + j];
            g_s[gm*16 + j] = v;
            atomicMax(&s_mk[j], fkey(v));
        }
    }
    __syncthreads();
    if (tid < 4){
        int j = h0 + (tid & 1) + (tid >> 1)*8;
        unsigned k = s_mk[j];
        if (k) atomicMax(&g_mkey[j], k);
    }
}

// ---------------- per-head Z (CSC order, warp per col) ----------------
__global__ __launch_bounds__(256) void k_Z(){
    __shared__ float sM[8];
    __shared__ float ssum[8];
    if (threadIdx.x < 8){
        float m = fdec(g_mkey[threadIdx.x]) + fdec(g_mkey[8 + threadIdx.x]);
        sM[threadIdx.x] = (m > 0.f) ? m : 0.01f*m;
        ssum[threadIdx.x] = 0.f;
    }
    __syncthreads();
    int warp = threadIdx.x >> 5, lane = threadIdx.x & 31;
    int hh = lane & 7, sub = lane >> 3;
    int c = blockIdx.x*8 + warp;
    float zacc = 0.f;
    if (c < NNODES){
        int p0 = g_colptr[c], p1 = g_colptr[c+1];
        if (p0 < p1){
            float sd = g_s[c*16 + 8 + hh];
            float Mh = sM[hh];
            for (int p = p0; p < p1; p += 4){
                int idx = p + sub;
                int rowv = g_srow[min(idx, p1-1)];
                float t = g_s[rowv*16 + hh] + sd;
                t = (t > 0.f) ? t : 0.01f*t;
                float w = __expf(t - Mh);
                if (idx < p1) zacc += w;
            }
        }
    }
    zacc += __shfl_xor_sync(0xffffffffu, zacc, 16);
    zacc += __shfl_xor_sync(0xffffffffu, zacc, 8);
    if (lane < 8) atomicAdd(&ssum[lane], zacc);
    __syncthreads();
    if (threadIdx.x < 8) atomicAdd(&g_Z[threadIdx.x], ssum[threadIdx.x]);
}

// ---------------- CSC scatter: warp per col, 4-edge unroll ----------------
__global__ __launch_bounds__(256) void k_scatter(float* __restrict__ out){
    __shared__ float sc[8];
    __shared__ float sMs[8];
    if (threadIdx.x < 8){
        sc[threadIdx.x] = g_gate[threadIdx.x] / g_Z[threadIdx.x];
        float m = fdec(g_mkey[threadIdx.x]) + fdec(g_mkey[8 + threadIdx.x]);
        sMs[threadIdx.x] = (m > 0.f) ? m : 0.01f*m;
    }
    __syncthreads();
    int warp = threadIdx.x >> 5, lane = threadIdx.x & 31;
    int c = blockIdx.x*8 + warp;
    if (c >= NNODES) return;
    int p0 = g_colptr[c], p1 = g_colptr[c+1];
    if (p0 == p1) return;
    const __half* wp = g_Wh16 + (size_t)c*NH;
    float whv[16];
#pragma unroll
    for (int h = 0; h < 8; h++){
        whv[h]     = __half2float(wp[h*64 + lane]);
        whv[8 + h] = __half2float(wp[h*64 + 32 + lane]);
    }
    int hh = lane & 7, sub = lane >> 3;
    float sd = g_s[c*16 + 8 + hh];
    float ch = sc[hh];
    float Mh = sMs[hh];

    for (int p = p0; p < p1; p += 4){
        int idx = p + sub;
        int rowv = g_srow[min(idx, p1-1)];
        float t = g_s[rowv*16 + hh] + sd;
        t = (t > 0.f) ? t : 0.01f*t;
        float wv = (idx < p1) ? ch * __expf(t - Mh) : 0.f;

        float a0l = 0.f, a0h = 0.f, a1l = 0.f, a1h = 0.f;
        float a2l = 0.f, a2h = 0.f, a3l = 0.f, a3h = 0.f;
#pragma unroll
        for (int h = 0; h < 8; h++){
            float w0 = __shfl_sync(0xffffffffu, wv, h);
            float w1 = __shfl_sync(0xffffffffu, wv, 8 + h);
            float w2 = __shfl_sync(0xffffffffu, wv, 16 + h);
            float w3 = __shfl_sync(0xffffffffu, wv, 24 + h);
            a0l += w0*whv[h];  a0h += w0*whv[8+h];
            a1l += w1*whv[h];  a1h += w1*whv[8+h];
            a2l += w2*whv[h];  a2h += w2*whv[8+h];
            a3l += w3*whv[h];  a3h += w3*whv[8+h];
        }
        int r0 = __shfl_sync(0xffffffffu, rowv, 0);
        int r1 = __shfl_sync(0xffffffffu, rowv, 8);
        int r2 = __shfl_sync(0xffffffffu, rowv, 16);
        int r3 = __shfl_sync(0xffffffffu, rowv, 24);
        atomicAdd(out + (size_t)r0*64 + lane,      a0l);
        atomicAdd(out + (size_t)r0*64 + 32 + lane, a0h);
        if (p + 1 < p1){
            atomicAdd(out + (size_t)r1*64 + lane,      a1l);
            atomicAdd(out + (size_t)r1*64 + 32 + lane, a1h);
        }
        if (p + 2 < p1){
            atomicAdd(out + (size_t)r2*64 + lane,      a2l);
            atomicAdd(out + (size_t)r2*64 + 32 + lane, a2h);
        }
        if (p + 3 < p1){
            atomicAdd(out + (size_t)r3*64 + lane,      a3l);
            atomicAdd(out + (size_t)r3*64 + 32 + lane, a3h);
        }
    }
}

// ---------------- launch ----------------
extern "C" void kernel_launch(void* const* d_in, const int* in_sizes, int n_in,
                              void* d_out, int out_size){
    const float* x    = (const float*)d_in[0];
    const int*   ei   = (const int*)  d_in[1];
    const float* W    = (const float*)d_in[2];
    const float* b    = (const float*)d_in[3];
    const float* a    = (const float*)d_in[4];
    const float* gate = (const float*)d_in[5];
    float* out = (float*)d_out;

    cudaFuncSetAttribute(k_big, cudaFuncAttributeMaxDynamicSharedMemorySize, SMEM_BIG);

    k_setup<<<(NPAD*IN_DIM/4 + 255)/256, 256>>>(x, ei, W, gate, out);
    k_scan1<<<(NNODES + 255)/256, 256>>>();
    k_scan23<<<(NNODES + 255)/256, 256>>>();
    dim3 gg(4, NPAD/128);
    k_big<<<gg, 512, SMEM_BIG>>>(b, a, ei);
    k_Z<<<(NNODES + 7)/8, 256>>>();
    k_scatter<<<(NNODES + 7)/8, 256>>>(out);
}

// round 16
// speedup vs baseline: 1.6826x; 1.3692x over previous
#include <cuda_runtime.h>
#include <cuda_fp16.h>
#include <stdint.h>

#define NNODES 50000
#define NPAD   50048            // 391 * 128
#define NEDGES 800000
#define IN_DIM 256
#define HEADS  8
#define NH     512

// ---------------- device scratch ----------------
__device__ __align__(128) __half g_Ah[(size_t)NPAD*IN_DIM];   // fp16 hi of x
__device__ __align__(128) __half g_Al[(size_t)NPAD*IN_DIM];   // fp16 lo of x
__device__ __align__(128) __half g_Bh[NH*IN_DIM];             // fp16 W^T
__device__ __align__(128) __half g_uh[16*IN_DIM];             // fp16 hi of u
__device__ __align__(128) __half g_ul[16*IN_DIM];             // fp16 lo of u
__device__ __align__(128) __half g_Wh16[(size_t)NNODES*NH];   // 51.2 MB fp16 Wh
__device__ __align__(16)  float g_s[NNODES*16];
__device__ float g_c[16];
__device__ unsigned g_mkey[16];
__device__ float g_Z[HEADS];
__device__ float g_gate[HEADS];
__device__ int g_cnt[NNODES];
__device__ int g_colptr[NNODES+1];
__device__ int g_cur[NNODES];
__device__ int g_bsum[256];
__device__ int g_srow[NEDGES];

// ---------------- helpers ----------------
__device__ __forceinline__ unsigned fkey(float f){
    unsigned b = __float_as_uint(f);
    return (b & 0x80000000u) ? ~b : (b | 0x80000000u);
}
__device__ __forceinline__ float fdec(unsigned k){
    return (k & 0x80000000u) ? __uint_as_float(k ^ 0x80000000u) : __uint_as_float(~k);
}
__device__ __forceinline__ uint32_t s2u(const void* p){
    return (uint32_t)__cvta_generic_to_shared(p);
}
__device__ __forceinline__ void cpa16(uint32_t dst, const void* src){
    asm volatile("cp.async.cg.shared.global [%0], [%1], 16;" :: "r"(dst), "l"(src));
}
__device__ __forceinline__ void ldsm4(uint32_t* r, uint32_t addr){
    asm volatile("ldmatrix.sync.aligned.m8n8.x4.shared.b16 {%0,%1,%2,%3}, [%4];"
        : "=r"(r[0]), "=r"(r[1]), "=r"(r[2]), "=r"(r[3]) : "r"(addr));
}
__device__ __forceinline__ void mma_f16(float* d, const uint32_t* a, uint32_t b0, uint32_t b1){
    asm volatile("mma.sync.aligned.m16n8k16.row.col.f32.f16.f16.f32 "
        "{%0,%1,%2,%3},{%4,%5,%6,%7},{%8,%9},{%0,%1,%2,%3};"
        : "+f"(d[0]), "+f"(d[1]), "+f"(d[2]), "+f"(d[3])
        : "r"(a[0]), "r"(a[1]), "r"(a[2]), "r"(a[3]), "r"(b0), "r"(b1));
}

// ---------------- fused setup ----------------
__global__ void k_setup(const float* __restrict__ x, const int* __restrict__ ei,
                        const float* __restrict__ W, const float* __restrict__ b,
                        const float* __restrict__ a, const float* __restrict__ gate,
                        float* __restrict__ out){
    int tid = blockIdx.x*blockDim.x + threadIdx.x;
    if (tid < 8)  g_Z[tid] = 0.f;
    if (tid < 16){
        g_mkey[tid] = 0u;
        int j = tid, h = j & 7, off = (j & 8) ? 64 : 0;
        float acc = 0.f;
        for (int o = 0; o < 64; o++)
            acc += b[h*64 + o] * a[h*128 + off + o];
        g_c[j] = acc;
    }
    if (tid == 0){
        float m = -1e30f;
        for (int h = 0; h < HEADS; h++) m = fmaxf(m, gate[h]);
        float ex[HEADS]; float z = 0.f;
        for (int h = 0; h < HEADS; h++){ ex[h] = __expf(gate[h]-m); z += ex[h]; }
        for (int h = 0; h < HEADS; h++) g_gate[h] = ex[h]/z;
    }
    if (tid < NNODES*16)
        reinterpret_cast<float4*>(out)[tid] = make_float4(0.f,0.f,0.f,0.f);
    if (tid < NEDGES) atomicAdd(&g_cnt[ei[NEDGES + tid]], 1);
    // u[j][d] = sum_o W[h][d][o] * a[h][off+o], fp16 hi/lo
    if (tid < 16*IN_DIM){
        int j = tid >> 8, dd = tid & 255;
        int h = j & 7, off = (j & 8) ? 64 : 0;
        const float* Wp = W + (size_t)h*IN_DIM*64 + dd*64;
        const float* ap = a + h*128 + off;
        float acc = 0.f;
#pragma unroll 8
        for (int o = 0; o < 64; o++) acc += Wp[o]*ap[o];
        __half hh = __float2half_rn(acc);
        g_uh[tid] = hh;
        g_ul[tid] = __float2half_rn(acc - __half2float(hh));
    }
    // W transpose to Bh[n][d], single fp16
    if (tid < NH*IN_DIM){
        int n = tid >> 8, d = tid & 255;
        int h = n >> 6, o = n & 63;
        g_Bh[tid] = __float2half_rn(W[(size_t)h*IN_DIM*64 + d*64 + o]);
    }
    // x -> fp16 hi/lo, padded
    if (tid < NPAD*IN_DIM/4){
        int base = tid*4;
        int row = base / IN_DIM;
        float4 v = make_float4(0.f,0.f,0.f,0.f);
        if (row < NNODES) v = *reinterpret_cast<const float4*>(x + base);
        float vv[4] = {v.x, v.y, v.z, v.w};
        unsigned short hb[4], lb[4];
#pragma unroll
        for (int j = 0; j < 4; j++){
            __half h = __float2half_rn(vv[j]);
            __half l = __float2half_rn(vv[j] - __half2float(h));
            hb[j] = __half_as_ushort(h);
            lb[j] = __half_as_ushort(l);
        }
        uint2 ph = make_uint2((unsigned)hb[0] | ((unsigned)hb[1]<<16),
                              (unsigned)hb[2] | ((unsigned)hb[3]<<16));
        uint2 pl = make_uint2((unsigned)lb[0] | ((unsigned)lb[1]<<16),
                              (unsigned)lb[2] | ((unsigned)lb[3]<<16));
        *reinterpret_cast<uint2*>(reinterpret_cast<char*>(g_Ah) + (size_t)base*2) = ph;
        *reinterpret_cast<uint2*>(reinterpret_cast<char*>(g_Al) + (size_t)base*2) = pl;
    }
}

// ---------------- CSC scans ----------------
__global__ void k_scan1(){
    __shared__ int sd[256];
    int tid = threadIdx.x;
    int i = blockIdx.x*256 + tid;
    int v = (i < NNODES) ? g_cnt[i] : 0;
    if (i < NNODES) g_cnt[i] = 0;
    sd[tid] = v; __syncthreads();
    for (int off = 1; off < 256; off <<= 1){
        int t = (tid >= off) ? sd[tid - off] : 0;
        __syncthreads();
        sd[tid] += t;
        __syncthreads();
    }
    if (i < NNODES) g_colptr[i] = sd[tid] - v;
    if (tid == 255) g_bsum[blockIdx.x] = sd[255];
}
__global__ void k_scan23(){
    __shared__ int sd[256];
    __shared__ int s_off;
    int tid = threadIdx.x;
    const int nb = (NNODES + 255)/256;
    int v = (tid < nb) ? g_bsum[tid] : 0;
    sd[tid] = v; __syncthreads();
    for (int off = 1; off < 256; off <<= 1){
        int t = (tid >= off) ? sd[tid - off] : 0;
        __syncthreads();
        sd[tid] += t;
        __syncthreads();
    }
    if (tid == (int)blockIdx.x) s_off = sd[tid] - v;
    __syncthreads();
    int i = blockIdx.x*256 + tid;
    if (i < NNODES){
        int p = g_colptr[i] + s_off;
        g_colptr[i] = p;
        g_cur[i]    = p;
    }
    if (blockIdx.x == 0 && tid == 0) g_colptr[NNODES] = NEDGES;
}

// ---------------- big kernel: SINGLE-PASS fp16 GEMM, 512 thr, 3-stage ----------------
#define BTILE    16384                  // 128 rows x 128 B (64 fp16 cols)
#define BST      32768                  // stage = A + B tile
#define SMEM_BIG 98304                  // 3 stages

__device__ __forceinline__ void load_tile64(uint32_t dstbase, const __half* __restrict__ src,
                                            int tid){
#pragma unroll
    for (int i = 0; i < 2; i++){
        int idx = tid + i*512;
        int r = idx >> 3, q = idx & 7;
        uint32_t off = (uint32_t)(r*128 + ((q ^ (r & 7)) << 4));
        cpa16(dstbase + off, src + (size_t)r*IN_DIM + q*8);
    }
}

__device__ __forceinline__ void gemm_stage64(uint32_t sb_st, int wm, int wn, int lane,
                                             float d[2][4][4]){
    int lr = lane & 15;
    int qh = lane >> 4;
    uint32_t arow[2], brow[2];
    int asw[2], bsw[2];
#pragma unroll
    for (int mi = 0; mi < 2; mi++){
        int row = wm + mi*16 + lr;
        arow[mi] = sb_st + row*128;
        asw[mi]  = row & 7;
    }
#pragma unroll
    for (int bi = 0; bi < 2; bi++){
        int row = wn + bi*16 + lr;
        brow[bi] = sb_st + BTILE + row*128;
        bsw[bi]  = row & 7;
    }
#pragma unroll
    for (int ks = 0; ks < 4; ks++){
        int q = ks*2 + qh;
        uint32_t af[2][4], bfr[2][4];
#pragma unroll
        for (int mi = 0; mi < 2; mi++)
            ldsm4(af[mi], arow[mi] + ((q ^ asw[mi]) << 4));
#pragma unroll
        for (int bi = 0; bi < 2; bi++)
            ldsm4(bfr[bi], brow[bi] + ((q ^ bsw[bi]) << 4));
#pragma unroll
        for (int mi = 0; mi < 2; mi++)
#pragma unroll
            for (int ni = 0; ni < 4; ni++){
                int bi = ni >> 1, sub = ni & 1;
                mma_f16(d[mi][ni], af[mi], bfr[bi][sub], bfr[bi][sub + 2]);
            }
    }
}

// grid = (4, 391), 512 threads
__global__ __launch_bounds__(512,2) void k_big(const float* __restrict__ bias,
                                               const int* __restrict__ ei){
    extern __shared__ char smem[];
    uint32_t sb = s2u(smem);

    int tid = threadIdx.x, wid = tid >> 5, lane = tid & 31;
    int wm = (wid >> 2)*32, wn = (wid & 3)*32;
    int m0 = blockIdx.y*128, n0 = blockIdx.x*128;

    float d[2][4][4];
#pragma unroll
    for (int mi = 0; mi < 2; mi++)
#pragma unroll
        for (int ni = 0; ni < 4; ni++)
#pragma unroll
            for (int k = 0; k < 4; k++) d[mi][ni][k] = 0.f;

    const __half* Abase = g_Ah + (size_t)m0*IN_DIM;
    const __half* Bbase = g_Bh + (size_t)n0*IN_DIM;

    // prologue: chunks 0,1 (K-chunks of 64)
#pragma unroll
    for (int c = 0; c < 2; c++){
        uint32_t st = sb + c*BST;
        load_tile64(st,         Abase + c*64, tid);
        load_tile64(st + BTILE, Bbase + c*64, tid);
        asm volatile("cp.async.commit_group;" ::: "memory");
    }

    // CSC reorder: 512 edges per CTA, hidden behind prologue loads
    {
        int e = (blockIdx.y*4 + blockIdx.x)*512 + tid;
        if (e < NEDGES){
            int row = ei[e], col = ei[NEDGES + e];
            int pos = atomicAdd(&g_cur[col], 1);
            g_srow[pos] = row;
        }
    }

    for (int c = 0; c < 4; c++){
        asm volatile("cp.async.wait_group 1;" ::: "memory");
        __syncthreads();
        int cn = c + 2;
        if (cn < 4){
            uint32_t st = sb + (cn % 3)*BST;
            load_tile64(st,         Abase + cn*64, tid);
            load_tile64(st + BTILE, Bbase + cn*64, tid);
        }
        asm volatile("cp.async.commit_group;" ::: "memory");
        gemm_stage64(sb + (c % 3)*BST, wm, wn, lane, d);
    }

    // -------- epilogue: bias + fp16 store only --------
#pragma unroll
    for (int mi = 0; mi < 2; mi++){
#pragma unroll
        for (int ni = 0; ni < 4; ni++){
            int C = wn + ni*8 + (lane & 3)*2;
            float b0 = __ldg(&bias[n0 + C]), b1 = __ldg(&bias[n0 + C + 1]);
#pragma unroll
            for (int rr = 0; rr < 2; rr++){
                float v0 = d[mi][ni][rr*2 + 0] + b0;
                float v1 = d[mi][ni][rr*2 + 1] + b1;
                int gm = m0 + wm + mi*16 + (lane >> 2) + rr*8;
                if (gm < NNODES){
                    __half2 hv = __floats2half2_rn(v0, v1);
                    *reinterpret_cast<__half2*>(g_Wh16 + (size_t)gm*NH + n0 + C) = hv;
                }
            }
        }
    }
}

// ---------------- k_s: precise s = x*u + c (3-pass fp16 split) + node max ----------------
#define SOFF_AL 65536
#define SOFF_UH 131072
#define SOFF_UL 139264
#define SMEM_S  147456

__global__ __launch_bounds__(256,1) void k_s(){
    extern __shared__ char smem[];
    uint32_t sb = s2u(smem);
    int tid = threadIdx.x, wid = tid >> 5, lane = tid & 31;
    int m0 = blockIdx.x*128;

    // one-shot load: Ah, Al (128x256 fp16 each, 512B rows), uh, ul (16x256)
#pragma unroll
    for (int i = 0; i < 16; i++){
        int idx = tid + i*256;
        int r = idx >> 5, q = idx & 31;
        uint32_t off = (uint32_t)(r*512 + ((q ^ (r & 7)) << 4));
        cpa16(sb + off,           g_Ah + (size_t)(m0 + r)*IN_DIM + q*8);
        cpa16(sb + SOFF_AL + off, g_Al + (size_t)(m0 + r)*IN_DIM + q*8);
    }
#pragma unroll
    for (int i = 0; i < 2; i++){
        int idx = tid + i*256;
        int r = idx >> 5, q = idx & 31;
        uint32_t off = (uint32_t)(r*512 + ((q ^ (r & 7)) << 4));
        cpa16(sb + SOFF_UH + off, g_uh + r*IN_DIM + q*8);
        cpa16(sb + SOFF_UL + off, g_ul + r*IN_DIM + q*8);
    }
    asm volatile("cp.async.commit_group;" ::: "memory");
    asm volatile("cp.async.wait_group 0;" ::: "memory");
    __syncthreads();

    int wm = wid*16;
    int lr = lane & 15, qh = lane >> 4;
    float d[2][4];
#pragma unroll
    for (int ni = 0; ni < 2; ni++)
#pragma unroll
        for (int k = 0; k < 4; k++) d[ni][k] = 0.f;

    uint32_t arow = sb + (wm + lr)*512;
    int asw = (wm + lr) & 7;
    uint32_t brow = sb + SOFF_UH + lr*512;
    int bsw = lr & 7;

#pragma unroll
    for (int pass = 0; pass < 3; pass++){
        uint32_t ab = arow + ((pass == 1) ? SOFF_AL : 0u);
        uint32_t bb = brow + ((pass == 2) ? (SOFF_UL - SOFF_UH) : 0u);
#pragma unroll
        for (int ks = 0; ks < 16; ks++){
            int q = ks*2 + qh;
            uint32_t af[4], bf[4];
            ldsm4(af, ab + ((q ^ asw) << 4));
            ldsm4(bf, bb + ((q ^ bsw) << 4));
            mma_f16(d[0], af, bf[0], bf[2]);
            mma_f16(d[1], af, bf[1], bf[3]);
        }
    }
    __syncthreads();

    // overlay: s_sm[128][16], mk[16], c[16]
    float*    s_sm = (float*)(smem);
    unsigned* s_mk = (unsigned*)(smem + 8192);
    float*    s_c  = (float*)(smem + 8320);
    if (tid < 16){ s_mk[tid] = 0u; s_c[tid] = g_c[tid]; }
    __syncthreads();
#pragma unroll
    for (int ni = 0; ni < 2; ni++){
        int c0 = ni*8 + (lane & 3)*2;
#pragma unroll
        for (int rr = 0; rr < 2; rr++){
            int row = wm + (lane >> 2) + rr*8;
            s_sm[row*16 + c0]     = d[ni][rr*2];
            s_sm[row*16 + c0 + 1] = d[ni][rr*2 + 1];
        }
    }
    __syncthreads();
#pragma unroll
    for (int i = tid; i < 2048; i += 256){
        int r = i >> 4, j = i & 15;
        int gm = m0 + r;
        if (gm < NNODES){
            float v = s_sm[i] + s_c[j];
            g_s[gm*16 + j] = v;
            atomicMax(&s_mk[j], fkey(v));
        }
    }
    __syncthreads();
    if (tid < 16){
        unsigned k = s_mk[tid];
        if (k) atomicMax(&g_mkey[tid], k);
    }
}

// ---------------- per-head Z (CSC order, warp per col) ----------------
__global__ __launch_bounds__(256) void k_Z(){
    __shared__ float sM[8];
    __shared__ float ssum[8];
    if (threadIdx.x < 8){
        float m = fdec(g_mkey[threadIdx.x]) + fdec(g_mkey[8 + threadIdx.x]);
        sM[threadIdx.x] = (m > 0.f) ? m : 0.01f*m;
        ssum[threadIdx.x] = 0.f;
    }
    __syncthreads();
    int warp = threadIdx.x >> 5, lane = threadIdx.x & 31;
    int hh = lane & 7, sub = lane >> 3;
    int c = blockIdx.x*8 + warp;
    float zacc = 0.f;
    if (c < NNODES){
        int p0 = g_colptr[c], p1 = g_colptr[c+1];
        if (p0 < p1){
            float sd = g_s[c*16 + 8 + hh];
            float Mh = sM[hh];
            for (int p = p0; p < p1; p += 4){
                int idx = p + sub;
                int rowv = g_srow[min(idx, p1-1)];
                float t = g_s[rowv*16 + hh] + sd;
                t = (t > 0.f) ? t : 0.01f*t;
                float w = __expf(t - Mh);
                if (idx < p1) zacc += w;
            }
        }
    }
    zacc += __shfl_xor_sync(0xffffffffu, zacc, 16);
    zacc += __shfl_xor_sync(0xffffffffu, zacc, 8);
    if (lane < 8) atomicAdd(&ssum[lane], zacc);
    __syncthreads();
    if (threadIdx.x < 8) atomicAdd(&g_Z[threadIdx.x], ssum[threadIdx.x]);
}

// ---------------- CSC scatter: warp per col, 4-edge unroll ----------------
__global__ __launch_bounds__(256) void k_scatter(float* __restrict__ out){
    __shared__ float sc[8];
    __shared__ float sMs[8];
    if (threadIdx.x < 8){
        sc[threadIdx.x] = g_gate[threadIdx.x] / g_Z[threadIdx.x];
        float m = fdec(g_mkey[threadIdx.x]) + fdec(g_mkey[8 + threadIdx.x]);
        sMs[threadIdx.x] = (m > 0.f) ? m : 0.01f*m;
    }
    __syncthreads();
    int warp = threadIdx.x >> 5, lane = threadIdx.x & 31;
    int c = blockIdx.x*8 + warp;
    if (c >= NNODES) return;
    int p0 = g_colptr[c], p1 = g_colptr[c+1];
    if (p0 == p1) return;
    const __half* wp = g_Wh16 + (size_t)c*NH;
    float whv[16];
#pragma unroll
    for (int h = 0; h < 8; h++){
        whv[h]     = __half2float(wp[h*64 + lane]);
        whv[8 + h] = __half2float(wp[h*64 + 32 + lane]);
    }
    int hh = lane & 7, sub = lane >> 3;
    float sd = g_s[c*16 + 8 + hh];
    float ch = sc[hh];
    float Mh = sMs[hh];

    for (int p = p0; p < p1; p += 4){
        int idx = p + sub;
        int rowv = g_srow[min(idx, p1-1)];
        float t = g_s[rowv*16 + hh] + sd;
        t = (t > 0.f) ? t : 0.01f*t;
        float wv = (idx < p1) ? ch * __expf(t - Mh) : 0.f;

        float a0l = 0.f, a0h = 0.f, a1l = 0.f, a1h = 0.f;
        float a2l = 0.f, a2h = 0.f, a3l = 0.f, a3h = 0.f;
#pragma unroll
        for (int h = 0; h < 8; h++){
            float w0 = __shfl_sync(0xffffffffu, wv, h);
            float w1 = __shfl_sync(0xffffffffu, wv, 8 + h);
            float w2 = __shfl_sync(0xffffffffu, wv, 16 + h);
            float w3 = __shfl_sync(0xffffffffu, wv, 24 + h);
            a0l += w0*whv[h];  a0h += w0*whv[8+h];
            a1l += w1*whv[h];  a1h += w1*whv[8+h];
            a2l += w2*whv[h];  a2h += w2*whv[8+h];
            a3l += w3*whv[h];  a3h += w3*whv[8+h];
        }
        int r0 = __shfl_sync(0xffffffffu, rowv, 0);
        int r1 = __shfl_sync(0xffffffffu, rowv, 8);
        int r2 = __shfl_sync(0xffffffffu, rowv, 16);
        int r3 = __shfl_sync(0xffffffffu, rowv, 24);
        atomicAdd(out + (size_t)r0*64 + lane,      a0l);
        atomicAdd(out + (size_t)r0*64 + 32 + lane, a0h);
        if (p + 1 < p1){
            atomicAdd(out + (size_t)r1*64 + lane,      a1l);
            atomicAdd(out + (size_t)r1*64 + 32 + lane, a1h);
        }
        if (p + 2 < p1){
            atomicAdd(out + (size_t)r2*64 + lane,      a2l);
            atomicAdd(out + (size_t)r2*64 + 32 + lane, a2h);
        }
        if (p + 3 < p1){
            atomicAdd(out + (size_t)r3*64 + lane,      a3l);
            atomicAdd(out + (size_t)r3*64 + 32 + lane, a3h);
        }
    }
}

// ---------------- launch ----------------
extern "C" void kernel_launch(void* const* d_in, const int* in_sizes, int n_in,
                              void* d_out, int out_size){
    const float* x    = (const float*)d_in[0];
    const int*   ei   = (const int*)  d_in[1];
    const float* W    = (const float*)d_in[2];
    const float* b    = (const float*)d_in[3];
    const float* a    = (const float*)d_in[4];
    const float* gate = (const float*)d_in[5];
    float* out = (float*)d_out;

    cudaFuncSetAttribute(k_big, cudaFuncAttributeMaxDynamicSharedMemorySize, SMEM_BIG);
    cudaFuncSetAttribute(k_s,   cudaFuncAttributeMaxDynamicSharedMemorySize, SMEM_S);

    k_setup<<<(NPAD*IN_DIM/4 + 255)/256, 256>>>(x, ei, W, b, a, gate, out);
    k_scan1<<<(NNODES + 255)/256, 256>>>();
    k_scan23<<<(NNODES + 255)/256, 256>>>();
    dim3 gg(4, NPAD/128);
    k_big<<<gg, 512, SMEM_BIG>>>(b, ei);       // ncu captured slot
    k_s<<<NPAD/128, 256, SMEM_S>>>();
    k_Z<<<(NNODES + 7)/8, 256>>>();
    k_scatter<<<(NNODES + 7)/8, 256>>>(out);
}